// round 5
// baseline (speedup 1.0000x reference)
#include <cuda_runtime.h>

#define Bn 4
#define Tn 2048
#define Cn 1024
#define Hn 16
#define Dn 64
// B*H*T*D = 8,388,608 floats per buffer
__device__ float g_q[Bn*Hn*Tn*Dn];
__device__ float g_k[Bn*Hn*Tn*Dn];
__device__ float g_v[Bn*Hn*Tn*Dn];
__device__ float g_attn[Bn*Hn*Tn*Dn];

// ---------------------------------------------------------------------------
// Kernel 1: QKV projection.  q[b,h,t,d] = sum_c x[b,t,c] * Wq[h,c,d]
// Viewed as GEMM: X[8192,1024] @ Wh[1024,64] per head.  BN=64 == one head.
// grid (16 heads, 128 m-tiles, 3 {q,k,v}), block 256.
// ---------------------------------------------------------------------------
__global__ __launch_bounds__(256) void qkv_kernel(
    const float* __restrict__ x,
    const float* __restrict__ Wq,
    const float* __restrict__ Wk,
    const float* __restrict__ Wv)
{
    __shared__ float As[16][68];   // [k][m], padded
    __shared__ float Bs[16][64];   // [k][d]

    const float* W  = (blockIdx.z == 0) ? Wq : (blockIdx.z == 1) ? Wk : Wv;
    float*       out = (blockIdx.z == 0) ? g_q : (blockIdx.z == 1) ? g_k : g_v;

    const int h  = blockIdx.x;
    const int m0 = blockIdx.y * 64;
    const int tid = threadIdx.x;
    const int tx = tid & 15, ty = tid >> 4;
    const int lr = tid >> 2, lc = (tid & 3) * 4;
    const float* Wh = W + (size_t)h * Cn * Dn;

    float acc[4][4] = {};

    for (int k0 = 0; k0 < Cn; k0 += 16) {
        float4 a = *(const float4*)&x[(size_t)(m0 + lr) * Cn + k0 + lc];
        As[lc+0][lr] = a.x; As[lc+1][lr] = a.y;
        As[lc+2][lr] = a.z; As[lc+3][lr] = a.w;
        #pragma unroll
        for (int i = 0; i < 4; ++i) {
            int idx = tid + i * 256;
            Bs[idx >> 6][idx & 63] = Wh[(size_t)(k0 + (idx >> 6)) * Dn + (idx & 63)];
        }
        __syncthreads();
        #pragma unroll
        for (int kk = 0; kk < 16; ++kk) {
            float4 av = *(const float4*)&As[kk][ty*4];
            float4 bv = *(const float4*)&Bs[kk][tx*4];
            float aa[4] = {av.x, av.y, av.z, av.w};
            float bb[4] = {bv.x, bv.y, bv.z, bv.w};
            #pragma unroll
            for (int i = 0; i < 4; ++i)
                #pragma unroll
                for (int j = 0; j < 4; ++j)
                    acc[i][j] += aa[i] * bb[j];
        }
        __syncthreads();
    }

    #pragma unroll
    for (int i = 0; i < 4; ++i) {
        int m = m0 + ty*4 + i;
        int b = m >> 11, t = m & 2047;
        float4 r = make_float4(acc[i][0], acc[i][1], acc[i][2], acc[i][3]);
        *(float4*)&out[((size_t)(b*Hn + h)*Tn + t)*Dn + tx*4] = r;
    }
}

// ---------------------------------------------------------------------------
// Kernel 2: causal flash attention per (b,h).  grid (32 q-tiles, 64 bh).
// 64 queries per block, D=64.  Online softmax, O accumulated in registers.
// Shared: Qt [d][r] (scaled), KP [d][s] for K^T then reused as P [r][s], V [s][d].
// 3 * 16KB = 48KB static shared.
// NOTE: tiles are 64x64 = 4096 floats; 256 threads must each load FOUR float4s
// (one per 16-column stripe).  [This was the round-1 bug: only cols 0..15 were
// loaded, leaving 75% of each tile uninitialized.]
// ---------------------------------------------------------------------------
__global__ __launch_bounds__(256, 2) void attn_kernel()
{
    __shared__ float Qt[64][64];
    __shared__ float KP[64][64];
    __shared__ float Vs[64][64];

    const int qt = gridDim.x - 1 - blockIdx.x;  // heavy tiles first
    const int bh = blockIdx.y;
    const int q0 = qt * 64;
    const int tid = threadIdx.x;
    const int tx = tid & 15, ty = tid >> 4;
    const int lr = tid >> 2, lc = (tid & 3) * 4;

    const float* qg = g_q + (size_t)bh * Tn * Dn;
    const float* kg = g_k + (size_t)bh * Tn * Dn;
    const float* vg = g_v + (size_t)bh * Tn * Dn;
    const float scale = 0.03125f;  // C^-0.5 = 1/32

    // load full Q tile transposed, pre-scaled: 4 stripes of 16 cols each
    #pragma unroll
    for (int c0 = 0; c0 < 64; c0 += 16) {
        float4 a = *(const float4*)&qg[(size_t)(q0 + lr) * Dn + c0 + lc];
        Qt[c0+lc+0][lr] = a.x * scale; Qt[c0+lc+1][lr] = a.y * scale;
        Qt[c0+lc+2][lr] = a.z * scale; Qt[c0+lc+3][lr] = a.w * scale;
    }

    float o[4][4] = {};
    float m_run[4], l_run[4];
    #pragma unroll
    for (int i = 0; i < 4; ++i) { m_run[i] = -1e30f; l_run[i] = 0.f; }

    for (int kt = 0; kt <= qt; ++kt) {
        const int k0 = kt * 64;
        __syncthreads();   // previous-iteration readers done (also covers Qt store, iter 0)
        // load full K tile transposed + full V tile natural
        #pragma unroll
        for (int c0 = 0; c0 < 64; c0 += 16) {
            float4 a = *(const float4*)&kg[(size_t)(k0 + lr) * Dn + c0 + lc];
            KP[c0+lc+0][lr] = a.x; KP[c0+lc+1][lr] = a.y;
            KP[c0+lc+2][lr] = a.z; KP[c0+lc+3][lr] = a.w;
            float4 v = *(const float4*)&vg[(size_t)(k0 + lr) * Dn + c0 + lc];
            *(float4*)&Vs[lr][c0+lc] = v;
        }
        __syncthreads();

        // S = (Q*scale) K^T  — 4x4 micro-tile per thread
        float s[4][4] = {};
        #pragma unroll 16
        for (int d = 0; d < 64; ++d) {
            float4 av = *(const float4*)&Qt[d][ty*4];
            float4 bv = *(const float4*)&KP[d][tx*4];
            float aa[4] = {av.x, av.y, av.z, av.w};
            float bb[4] = {bv.x, bv.y, bv.z, bv.w};
            #pragma unroll
            for (int i = 0; i < 4; ++i)
                #pragma unroll
                for (int j = 0; j < 4; ++j)
                    s[i][j] += aa[i] * bb[j];
        }

        if (kt == qt) {   // diagonal tile: mask cols > rows
            #pragma unroll
            for (int i = 0; i < 4; ++i)
                #pragma unroll
                for (int j = 0; j < 4; ++j)
                    if (tx*4 + j > ty*4 + i) s[i][j] = -1e30f;
        }

        // row max across the 16 lanes covering each row
        float mt[4];
        #pragma unroll
        for (int i = 0; i < 4; ++i)
            mt[i] = fmaxf(fmaxf(s[i][0], s[i][1]), fmaxf(s[i][2], s[i][3]));
        #pragma unroll
        for (int off = 8; off; off >>= 1)
            #pragma unroll
            for (int i = 0; i < 4; ++i)
                mt[i] = fmaxf(mt[i], __shfl_xor_sync(0xffffffffu, mt[i], off));

        float lsum[4];
        #pragma unroll
        for (int i = 0; i < 4; ++i) {
            float mn = fmaxf(m_run[i], mt[i]);
            float f  = __expf(m_run[i] - mn);
            m_run[i] = mn;
            lsum[i] = 0.f;
            #pragma unroll
            for (int j = 0; j < 4; ++j) {
                s[i][j] = __expf(s[i][j] - mn);
                lsum[i] += s[i][j];
            }
            #pragma unroll
            for (int j = 0; j < 4; ++j) o[i][j] *= f;
            l_run[i] *= f;
        }
        #pragma unroll
        for (int off = 8; off; off >>= 1)
            #pragma unroll
            for (int i = 0; i < 4; ++i)
                lsum[i] += __shfl_xor_sync(0xffffffffu, lsum[i], off);
        #pragma unroll
        for (int i = 0; i < 4; ++i) l_run[i] += lsum[i];

        __syncthreads();   // everyone done reading K^T
        #pragma unroll
        for (int i = 0; i < 4; ++i)
            *(float4*)&KP[ty*4+i][tx*4] = make_float4(s[i][0], s[i][1], s[i][2], s[i][3]);
        __syncthreads();

        // O += P @ V, 4 s-columns at a time (all LDS.128)
        #pragma unroll 4
        for (int s4 = 0; s4 < 16; ++s4) {
            float4 p[4], v[4];
            #pragma unroll
            for (int i = 0; i < 4; ++i) p[i] = *(const float4*)&KP[ty*4+i][s4*4];
            #pragma unroll
            for (int t = 0; t < 4; ++t) v[t] = *(const float4*)&Vs[s4*4+t][tx*4];
            #pragma unroll
            for (int i = 0; i < 4; ++i) {
                o[i][0] += p[i].x*v[0].x + p[i].y*v[1].x + p[i].z*v[2].x + p[i].w*v[3].x;
                o[i][1] += p[i].x*v[0].y + p[i].y*v[1].y + p[i].z*v[2].y + p[i].w*v[3].y;
                o[i][2] += p[i].x*v[0].z + p[i].y*v[1].z + p[i].z*v[2].z + p[i].w*v[3].z;
                o[i][3] += p[i].x*v[0].w + p[i].y*v[1].w + p[i].z*v[2].w + p[i].w*v[3].w;
            }
        }
    }

    #pragma unroll
    for (int i = 0; i < 4; ++i) {
        float inv = 1.0f / l_run[i];
        float4 r = make_float4(o[i][0]*inv, o[i][1]*inv, o[i][2]*inv, o[i][3]*inv);
        *(float4*)&g_attn[((size_t)bh*Tn + q0 + ty*4 + i)*Dn + tx*4] = r;
    }
}

// ---------------------------------------------------------------------------
// Kernel 3: output projection.  out[m,e] = sum_c A[m,c] * Wo[e,c] + bo[e]
// A gathered from g_attn [B,H,T,D].  grid (16 n-tiles, 128 m-tiles).
// ---------------------------------------------------------------------------
__global__ __launch_bounds__(256) void outproj_kernel(
    const float* __restrict__ Wo,
    const float* __restrict__ bo,
    float* __restrict__ out)
{
    __shared__ float As[16][68];   // [c][m]
    __shared__ float Bs[16][68];   // [c][e]

    const int n0 = blockIdx.x * 64;
    const int m0 = blockIdx.y * 64;
    const int tid = threadIdx.x;
    const int tx = tid & 15, ty = tid >> 4;
    const int lr = tid >> 2, lc = (tid & 3) * 4;

    float acc[4][4] = {};

    for (int k0 = 0; k0 < Cn; k0 += 16) {
        // A tile: rows m, cols c = k0+lc..+3 (all within one head since k0%64+15<64)
        {
            int m = m0 + lr;
            int head = k0 >> 6;
            int dofs = (k0 & 63) + lc;
            const float* ap = g_attn + ((size_t)(m >> 11)*Hn + head)*Tn*Dn
                                      + (size_t)(m & 2047)*Dn + dofs;
            float4 a = *(const float4*)ap;
            As[lc+0][lr] = a.x; As[lc+1][lr] = a.y;
            As[lc+2][lr] = a.z; As[lc+3][lr] = a.w;
        }
        // B tile: Bs[c][e] = Wo[(n0+e)*C + k0+c]
        {
            float4 w = *(const float4*)&Wo[(size_t)(n0 + lr) * Cn + k0 + lc];
            Bs[lc+0][lr] = w.x; Bs[lc+1][lr] = w.y;
            Bs[lc+2][lr] = w.z; Bs[lc+3][lr] = w.w;
        }
        __syncthreads();
        #pragma unroll
        for (int kk = 0; kk < 16; ++kk) {
            float4 av = *(const float4*)&As[kk][ty*4];
            float4 bv = *(const float4*)&Bs[kk][tx*4];
            float aa[4] = {av.x, av.y, av.z, av.w};
            float bb[4] = {bv.x, bv.y, bv.z, bv.w};
            #pragma unroll
            for (int i = 0; i < 4; ++i)
                #pragma unroll
                for (int j = 0; j < 4; ++j)
                    acc[i][j] += aa[i] * bb[j];
        }
        __syncthreads();
    }

    float4 bias = *(const float4*)&bo[n0 + tx*4];
    #pragma unroll
    for (int i = 0; i < 4; ++i) {
        int m = m0 + ty*4 + i;
        float4 r = make_float4(acc[i][0] + bias.x, acc[i][1] + bias.y,
                               acc[i][2] + bias.z, acc[i][3] + bias.w);
        *(float4*)&out[(size_t)m * Cn + n0 + tx*4] = r;
    }
}

// ---------------------------------------------------------------------------
extern "C" void kernel_launch(void* const* d_in, const int* in_sizes, int n_in,
                              void* d_out, int out_size)
{
    const float* x  = (const float*)d_in[0];
    const float* Wq = (const float*)d_in[1];
    const float* Wk = (const float*)d_in[2];
    const float* Wv = (const float*)d_in[3];
    const float* Wo = (const float*)d_in[4];
    const float* bo = (const float*)d_in[5];
    float* out = (float*)d_out;

    dim3 g1(Cn/Dn, (Bn*Tn)/64, 3);          // (16, 128, 3)
    qkv_kernel<<<g1, 256>>>(x, Wq, Wk, Wv);

    dim3 g2(Tn/64, Bn*Hn);                  // (32, 64)
    attn_kernel<<<g2, 256>>>();

    dim3 g3(Cn/64, (Bn*Tn)/64);             // (16, 128)
    outproj_kernel<<<g3, 256>>>(Wo, bo, out);
}

// round 7
// speedup vs baseline: 1.0034x; 1.0034x over previous
#include <cuda_runtime.h>

#define Bn 4
#define Tn 2048
#define Cn 1024
#define Hn 16
#define Dn 64
// B*H*T*D = 8,388,608 floats per buffer
__device__ float g_q[Bn*Hn*Tn*Dn];
__device__ float g_k[Bn*Hn*Tn*Dn];
__device__ float g_v[Bn*Hn*Tn*Dn];
__device__ float g_attn[Bn*Hn*Tn*Dn];

// ---------------------------------------------------------------------------
// Kernel 1: QKV projection.  q[b,h,t,d] = sum_c x[b,t,c] * Wq[h,c,d]
// Viewed as GEMM: X[8192,1024] @ Wh[1024,64] per head.  BN=64 == one head.
// grid (16 heads, 128 m-tiles, 3 {q,k,v}), block 256.
// ---------------------------------------------------------------------------
__global__ __launch_bounds__(256) void qkv_kernel(
    const float* __restrict__ x,
    const float* __restrict__ Wq,
    const float* __restrict__ Wk,
    const float* __restrict__ Wv)
{
    __shared__ float As[16][68];   // [k][m], padded
    __shared__ float Bs[16][64];   // [k][d]

    const float* W  = (blockIdx.z == 0) ? Wq : (blockIdx.z == 1) ? Wk : Wv;
    float*       out = (blockIdx.z == 0) ? g_q : (blockIdx.z == 1) ? g_k : g_v;

    const int h  = blockIdx.x;
    const int m0 = blockIdx.y * 64;
    const int tid = threadIdx.x;
    const int tx = tid & 15, ty = tid >> 4;
    const int lr = tid >> 2, lc = (tid & 3) * 4;
    const float* Wh = W + (size_t)h * Cn * Dn;

    float acc[4][4] = {};

    for (int k0 = 0; k0 < Cn; k0 += 16) {
        float4 a = *(const float4*)&x[(size_t)(m0 + lr) * Cn + k0 + lc];
        As[lc+0][lr] = a.x; As[lc+1][lr] = a.y;
        As[lc+2][lr] = a.z; As[lc+3][lr] = a.w;
        #pragma unroll
        for (int i = 0; i < 4; ++i) {
            int idx = tid + i * 256;
            Bs[idx >> 6][idx & 63] = Wh[(size_t)(k0 + (idx >> 6)) * Dn + (idx & 63)];
        }
        __syncthreads();
        #pragma unroll
        for (int kk = 0; kk < 16; ++kk) {
            float4 av = *(const float4*)&As[kk][ty*4];
            float4 bv = *(const float4*)&Bs[kk][tx*4];
            float aa[4] = {av.x, av.y, av.z, av.w};
            float bb[4] = {bv.x, bv.y, bv.z, bv.w};
            #pragma unroll
            for (int i = 0; i < 4; ++i)
                #pragma unroll
                for (int j = 0; j < 4; ++j)
                    acc[i][j] += aa[i] * bb[j];
        }
        __syncthreads();
    }

    #pragma unroll
    for (int i = 0; i < 4; ++i) {
        int m = m0 + ty*4 + i;
        int b = m >> 11, t = m & 2047;
        float4 r = make_float4(acc[i][0], acc[i][1], acc[i][2], acc[i][3]);
        *(float4*)&out[((size_t)(b*Hn + h)*Tn + t)*Dn + tx*4] = r;
    }
}

// ---------------------------------------------------------------------------
// Kernel 2: causal flash attention per (b,h).  grid (32 q-tiles, 64 bh).
// 64 queries per block, D=64.  Online softmax, O accumulated in registers.
// Shared: Qt [d][r] (scaled), KP [d][s] for K^T then reused as P [r][s], V [s][d].
// 3 * 16KB = 48KB static shared.
// NOTE: tiles are 64x64 = 4096 floats; 256 threads must each load FOUR float4s
// (one per 16-column stripe).  [This was the round-1 bug: only cols 0..15 were
// loaded, leaving 75% of each tile uninitialized.]
// ---------------------------------------------------------------------------
__global__ __launch_bounds__(256, 2) void attn_kernel()
{
    __shared__ float Qt[64][64];
    __shared__ float KP[64][64];
    __shared__ float Vs[64][64];

    const int qt = gridDim.x - 1 - blockIdx.x;  // heavy tiles first
    const int bh = blockIdx.y;
    const int q0 = qt * 64;
    const int tid = threadIdx.x;
    const int tx = tid & 15, ty = tid >> 4;
    const int lr = tid >> 2, lc = (tid & 3) * 4;

    const float* qg = g_q + (size_t)bh * Tn * Dn;
    const float* kg = g_k + (size_t)bh * Tn * Dn;
    const float* vg = g_v + (size_t)bh * Tn * Dn;
    const float scale = 0.03125f;  // C^-0.5 = 1/32

    // load full Q tile transposed, pre-scaled: 4 stripes of 16 cols each
    #pragma unroll
    for (int c0 = 0; c0 < 64; c0 += 16) {
        float4 a = *(const float4*)&qg[(size_t)(q0 + lr) * Dn + c0 + lc];
        Qt[c0+lc+0][lr] = a.x * scale; Qt[c0+lc+1][lr] = a.y * scale;
        Qt[c0+lc+2][lr] = a.z * scale; Qt[c0+lc+3][lr] = a.w * scale;
    }

    float o[4][4] = {};
    float m_run[4], l_run[4];
    #pragma unroll
    for (int i = 0; i < 4; ++i) { m_run[i] = -1e30f; l_run[i] = 0.f; }

    for (int kt = 0; kt <= qt; ++kt) {
        const int k0 = kt * 64;
        __syncthreads();   // previous-iteration readers done (also covers Qt store, iter 0)
        // load full K tile transposed + full V tile natural
        #pragma unroll
        for (int c0 = 0; c0 < 64; c0 += 16) {
            float4 a = *(const float4*)&kg[(size_t)(k0 + lr) * Dn + c0 + lc];
            KP[c0+lc+0][lr] = a.x; KP[c0+lc+1][lr] = a.y;
            KP[c0+lc+2][lr] = a.z; KP[c0+lc+3][lr] = a.w;
            float4 v = *(const float4*)&vg[(size_t)(k0 + lr) * Dn + c0 + lc];
            *(float4*)&Vs[lr][c0+lc] = v;
        }
        __syncthreads();

        // S = (Q*scale) K^T  — 4x4 micro-tile per thread
        float s[4][4] = {};
        #pragma unroll 16
        for (int d = 0; d < 64; ++d) {
            float4 av = *(const float4*)&Qt[d][ty*4];
            float4 bv = *(const float4*)&KP[d][tx*4];
            float aa[4] = {av.x, av.y, av.z, av.w};
            float bb[4] = {bv.x, bv.y, bv.z, bv.w};
            #pragma unroll
            for (int i = 0; i < 4; ++i)
                #pragma unroll
                for (int j = 0; j < 4; ++j)
                    s[i][j] += aa[i] * bb[j];
        }

        if (kt == qt) {   // diagonal tile: mask cols > rows
            #pragma unroll
            for (int i = 0; i < 4; ++i)
                #pragma unroll
                for (int j = 0; j < 4; ++j)
                    if (tx*4 + j > ty*4 + i) s[i][j] = -1e30f;
        }

        // row max across the 16 lanes covering each row
        float mt[4];
        #pragma unroll
        for (int i = 0; i < 4; ++i)
            mt[i] = fmaxf(fmaxf(s[i][0], s[i][1]), fmaxf(s[i][2], s[i][3]));
        #pragma unroll
        for (int off = 8; off; off >>= 1)
            #pragma unroll
            for (int i = 0; i < 4; ++i)
                mt[i] = fmaxf(mt[i], __shfl_xor_sync(0xffffffffu, mt[i], off));

        float lsum[4];
        #pragma unroll
        for (int i = 0; i < 4; ++i) {
            float mn = fmaxf(m_run[i], mt[i]);
            float f  = __expf(m_run[i] - mn);
            m_run[i] = mn;
            lsum[i] = 0.f;
            #pragma unroll
            for (int j = 0; j < 4; ++j) {
                s[i][j] = __expf(s[i][j] - mn);
                lsum[i] += s[i][j];
            }
            #pragma unroll
            for (int j = 0; j < 4; ++j) o[i][j] *= f;
            l_run[i] *= f;
        }
        #pragma unroll
        for (int off = 8; off; off >>= 1)
            #pragma unroll
            for (int i = 0; i < 4; ++i)
                lsum[i] += __shfl_xor_sync(0xffffffffu, lsum[i], off);
        #pragma unroll
        for (int i = 0; i < 4; ++i) l_run[i] += lsum[i];

        __syncthreads();   // everyone done reading K^T
        #pragma unroll
        for (int i = 0; i < 4; ++i)
            *(float4*)&KP[ty*4+i][tx*4] = make_float4(s[i][0], s[i][1], s[i][2], s[i][3]);
        __syncthreads();

        // O += P @ V, 4 s-columns at a time (all LDS.128)
        #pragma unroll 4
        for (int s4 = 0; s4 < 16; ++s4) {
            float4 p[4], v[4];
            #pragma unroll
            for (int i = 0; i < 4; ++i) p[i] = *(const float4*)&KP[ty*4+i][s4*4];
            #pragma unroll
            for (int t = 0; t < 4; ++t) v[t] = *(const float4*)&Vs[s4*4+t][tx*4];
            #pragma unroll
            for (int i = 0; i < 4; ++i) {
                o[i][0] += p[i].x*v[0].x + p[i].y*v[1].x + p[i].z*v[2].x + p[i].w*v[3].x;
                o[i][1] += p[i].x*v[0].y + p[i].y*v[1].y + p[i].z*v[2].y + p[i].w*v[3].y;
                o[i][2] += p[i].x*v[0].z + p[i].y*v[1].z + p[i].z*v[2].z + p[i].w*v[3].z;
                o[i][3] += p[i].x*v[0].w + p[i].y*v[1].w + p[i].z*v[2].w + p[i].w*v[3].w;
            }
        }
    }

    #pragma unroll
    for (int i = 0; i < 4; ++i) {
        float inv = 1.0f / l_run[i];
        float4 r = make_float4(o[i][0]*inv, o[i][1]*inv, o[i][2]*inv, o[i][3]*inv);
        *(float4*)&g_attn[((size_t)bh*Tn + q0 + ty*4 + i)*Dn + tx*4] = r;
    }
}

// ---------------------------------------------------------------------------
// Kernel 3: output projection.  out[m,e] = sum_c A[m,c] * Wo[e,c] + bo[e]
// A gathered from g_attn [B,H,T,D].  grid (16 n-tiles, 128 m-tiles).
// ---------------------------------------------------------------------------
__global__ __launch_bounds__(256) void outproj_kernel(
    const float* __restrict__ Wo,
    const float* __restrict__ bo,
    float* __restrict__ out)
{
    __shared__ float As[16][68];   // [c][m]
    __shared__ float Bs[16][68];   // [c][e]

    const int n0 = blockIdx.x * 64;
    const int m0 = blockIdx.y * 64;
    const int tid = threadIdx.x;
    const int tx = tid & 15, ty = tid >> 4;
    const int lr = tid >> 2, lc = (tid & 3) * 4;

    float acc[4][4] = {};

    for (int k0 = 0; k0 < Cn; k0 += 16) {
        // A tile: rows m, cols c = k0+lc..+3 (all within one head since k0%64+15<64)
        {
            int m = m0 + lr;
            int head = k0 >> 6;
            int dofs = (k0 & 63) + lc;
            const float* ap = g_attn + ((size_t)(m >> 11)*Hn + head)*Tn*Dn
                                      + (size_t)(m & 2047)*Dn + dofs;
            float4 a = *(const float4*)ap;
            As[lc+0][lr] = a.x; As[lc+1][lr] = a.y;
            As[lc+2][lr] = a.z; As[lc+3][lr] = a.w;
        }
        // B tile: Bs[c][e] = Wo[(n0+e)*C + k0+c]
        {
            float4 w = *(const float4*)&Wo[(size_t)(n0 + lr) * Cn + k0 + lc];
            Bs[lc+0][lr] = w.x; Bs[lc+1][lr] = w.y;
            Bs[lc+2][lr] = w.z; Bs[lc+3][lr] = w.w;
        }
        __syncthreads();
        #pragma unroll
        for (int kk = 0; kk < 16; ++kk) {
            float4 av = *(const float4*)&As[kk][ty*4];
            float4 bv = *(const float4*)&Bs[kk][tx*4];
            float aa[4] = {av.x, av.y, av.z, av.w};
            float bb[4] = {bv.x, bv.y, bv.z, bv.w};
            #pragma unroll
            for (int i = 0; i < 4; ++i)
                #pragma unroll
                for (int j = 0; j < 4; ++j)
                    acc[i][j] += aa[i] * bb[j];
        }
        __syncthreads();
    }

    float4 bias = *(const float4*)&bo[n0 + tx*4];
    #pragma unroll
    for (int i = 0; i < 4; ++i) {
        int m = m0 + ty*4 + i;
        float4 r = make_float4(acc[i][0] + bias.x, acc[i][1] + bias.y,
                               acc[i][2] + bias.z, acc[i][3] + bias.w);
        *(float4*)&out[(size_t)m * Cn + n0 + tx*4] = r;
    }
}

// ---------------------------------------------------------------------------
extern "C" void kernel_launch(void* const* d_in, const int* in_sizes, int n_in,
                              void* d_out, int out_size)
{
    const float* x  = (const float*)d_in[0];
    const float* Wq = (const float*)d_in[1];
    const float* Wk = (const float*)d_in[2];
    const float* Wv = (const float*)d_in[3];
    const float* Wo = (const float*)d_in[4];
    const float* bo = (const float*)d_in[5];
    float* out = (float*)d_out;

    dim3 g1(Cn/Dn, (Bn*Tn)/64, 3);          // (16, 128, 3)
    qkv_kernel<<<g1, 256>>>(x, Wq, Wk, Wv);

    dim3 g2(Tn/64, Bn*Hn);                  // (32, 64)
    attn_kernel<<<g2, 256>>>();

    dim3 g3(Cn/64, (Bn*Tn)/64);             // (16, 128)
    outproj_kernel<<<g3, 256>>>(Wo, bo, out);
}

// round 13
// speedup vs baseline: 1.5364x; 1.5311x over previous
#include <cuda_runtime.h>
#include <cuda_bf16.h>
#include <cstdint>

#define Bn 4
#define Tn 2048
#define Cn 1024
#define Hn 16
#define Dn 64

// f32 intermediates for the SIMT attention stage
__device__ float g_q[Bn*Hn*Tn*Dn];
__device__ float g_k[Bn*Hn*Tn*Dn];
__device__ float g_v[Bn*Hn*Tn*Dn];
// attention output as split-bf16 (consumed by HMMA outproj)
__device__ unsigned short g_attn_hi[Bn*Hn*Tn*Dn];
__device__ unsigned short g_attn_lo[Bn*Hn*Tn*Dn];
// transposed+split weights, K-major for the mma B operand
__device__ unsigned short g_wt_hi[3*Hn*Dn*Cn];   // [mat][h][d][c]
__device__ unsigned short g_wt_lo[3*Hn*Dn*Cn];
__device__ unsigned short g_wo_hi[Cn*Cn];        // [e][c] (already K-major)
__device__ unsigned short g_wo_lo[Cn*Cn];

// ---------------------------------------------------------------------------
// Helpers: baseline-PTX tensor core ops (no 'a'-suffix features!)
// ---------------------------------------------------------------------------
__device__ __forceinline__ uint32_t smem_u32(const void* p) {
    uint32_t a;
    asm("{ .reg .u64 t; cvta.to.shared.u64 t, %1; cvt.u32.u64 %0, t; }"
        : "=r"(a) : "l"(p));
    return a;
}
#define LDSM_X4(r, addr)                                                     \
    asm volatile("ldmatrix.sync.aligned.m8n8.x4.shared.b16 {%0,%1,%2,%3}, [%4];" \
        : "=r"((r)[0]), "=r"((r)[1]), "=r"((r)[2]), "=r"((r)[3]) : "r"(addr))
#define LDSM_X2(r, addr)                                                     \
    asm volatile("ldmatrix.sync.aligned.m8n8.x2.shared.b16 {%0,%1}, [%2];"   \
        : "=r"((r)[0]), "=r"((r)[1]) : "r"(addr))
#define MMA16816(d, a, b)                                                    \
    asm volatile("mma.sync.aligned.m16n8k16.row.col.f32.bf16.bf16.f32 "      \
        "{%0,%1,%2,%3}, {%4,%5,%6,%7}, {%8,%9}, {%0,%1,%2,%3};"              \
        : "+f"((d)[0]), "+f"((d)[1]), "+f"((d)[2]), "+f"((d)[3])             \
        : "r"((a)[0]), "r"((a)[1]), "r"((a)[2]), "r"((a)[3]),                \
          "r"((b)[0]), "r"((b)[1]))

#define SWZ(x) ((x) ^ (((x) >> 3) & 0x70))

__device__ __forceinline__ void bsplit(float v, unsigned short& hi, unsigned short& lo) {
    __nv_bfloat16 h = __float2bfloat16(v);
    hi = __bfloat16_as_ushort(h);
    lo = __bfloat16_as_ushort(__float2bfloat16(v - __bfloat162float(h)));
}
__device__ __forceinline__ uint2 pack4(unsigned short a, unsigned short b,
                                       unsigned short c, unsigned short d) {
    uint2 u;
    u.x = (uint32_t)a | ((uint32_t)b << 16);
    u.y = (uint32_t)c | ((uint32_t)d << 16);
    return u;
}

// ---------------------------------------------------------------------------
// Prep 1: transpose + split Wq/Wk/Wv:  g_wt[mat][h][d][c] = split(W[mat][h][c][d])
// ---------------------------------------------------------------------------
__global__ __launch_bounds__(256) void wsplit_t(
    const float* __restrict__ Wq, const float* __restrict__ Wk,
    const float* __restrict__ Wv)
{
    __shared__ float tile[64][65];
    const int mat = blockIdx.z, h = blockIdx.y, c0 = blockIdx.x * 64;
    const float* Wh = (mat == 0 ? Wq : mat == 1 ? Wk : Wv) + (size_t)h * Cn * Dn;
    const int tid = threadIdx.x;
    for (int i = tid; i < 4096; i += 256) {
        int r = i >> 6, d = i & 63;
        tile[r][d] = Wh[(size_t)(c0 + r) * Dn + d];
    }
    __syncthreads();
    for (int i = tid; i < 4096; i += 256) {
        int d = i >> 6, c = i & 63;
        unsigned short hi, lo; bsplit(tile[c][d], hi, lo);
        size_t o = ((size_t)(mat * Hn + h) * Dn + d) * Cn + c0 + c;
        g_wt_hi[o] = hi; g_wt_lo[o] = lo;
    }
}

// Prep 2: split Wo (already K-major: Wo[e][c])
__global__ __launch_bounds__(256) void wo_split(const float* __restrict__ Wo)
{
    int i = blockIdx.x * 256 + threadIdx.x;
    unsigned short hi, lo; bsplit(Wo[i], hi, lo);
    g_wo_hi[i] = hi; g_wo_lo[i] = lo;
}

// ---------------------------------------------------------------------------
// Kernel 1: QKV projection via mma.sync bf16 (split 3-term).
// Per CTA: one head, M=128 x-rows, N=192 (q|k|v, 64 each), K=1024.
// 8 warps: 4 m-stripes x 2 n-stripes; warp tile 32 x 96 (2 m-frag x 12 n-frag).
// grid (16 heads, 64 m-tiles), 256 threads, 80KB dyn smem.
// ---------------------------------------------------------------------------
#define QKV_A_HI 0
#define QKV_A_LO 16384
#define QKV_B_HI 32768
#define QKV_B_LO 57344
#define QKV_SMEM 81920

__global__ __launch_bounds__(256, 1) void qkv_tc(const float* __restrict__ x)
{
    extern __shared__ __align__(1024) char smem[];
    const uint32_t sb = smem_u32(smem);
    const int tid = threadIdx.x;
    const int h  = blockIdx.x;
    const int m0 = blockIdx.y * 128;
    const int wid = tid >> 5, L = tid & 31;
    const int wm = wid & 3, wn = wid >> 2;

    // ldmatrix lane address components
    const int a_r = L & 15;              // A row within 16
    const int a_k = (L >> 4) * 8;        // A k offset 0/8
    const int b_r = L & 7;               // B n row within 8
    const int b_k = (L & 8);             // B k offset 0/8

    float acc[2][12][4] = {};

    const int lrow = tid >> 1;           // A gmem load: row 0..127
    const int lpart = (tid & 1) * 32;    // half-row of 32 floats

    for (int chunk = 0; chunk < 16; ++chunk) {
        const int k0 = chunk * 64;
        if (chunk) __syncthreads();      // previous compute done before overwrite
        // ---- A: x chunk [128 x 64] f32 -> split bf16 hi/lo, SW128
        #pragma unroll
        for (int i = 0; i < 8; ++i) {
            int col = lpart + i * 4;
            float4 a = *(const float4*)&x[(size_t)(m0 + lrow) * Cn + k0 + col];
            unsigned short h0,h1,h2,h3,l0,l1,l2,l3;
            bsplit(a.x, h0, l0); bsplit(a.y, h1, l1);
            bsplit(a.z, h2, l2); bsplit(a.w, h3, l3);
            uint32_t off = SWZ((uint32_t)(lrow * 128 + col * 2));
            *(uint2*)(smem + QKV_A_HI + off) = pack4(h0, h1, h2, h3);
            *(uint2*)(smem + QKV_A_LO + off) = pack4(l0, l1, l2, l3);
        }
        // ---- B: [192 x 64] hi/lo from pre-split g_wt (rows: mat*64 + d)
        #pragma unroll
        for (int p = 0; p < 12; ++p) {
            int i = p * 256 + tid;           // 3072 uint2 per split
            int row = i >> 4, kk = (i & 15) * 4;
            int mat = row >> 6, d = row & 63;
            size_t src = ((size_t)(mat * Hn + h) * Dn + d) * Cn + k0 + kk;
            uint32_t off = SWZ((uint32_t)(row * 128 + kk * 2));
            *(uint2*)(smem + QKV_B_HI + off) = *(const uint2*)&g_wt_hi[src];
            *(uint2*)(smem + QKV_B_LO + off) = *(const uint2*)&g_wt_lo[src];
        }
        __syncthreads();

        #pragma unroll
        for (int ks = 0; ks < 4; ++ks) {
            const int kb = ks * 16;
            uint32_t ah[2][4], al[2][4];
            #pragma unroll
            for (int mi = 0; mi < 2; ++mi) {
                uint32_t aoff = SWZ((uint32_t)((wm*32 + mi*16 + a_r) * 128 + (kb + a_k) * 2));
                LDSM_X4(ah[mi], sb + QKV_A_HI + aoff);
                LDSM_X4(al[mi], sb + QKV_A_LO + aoff);
            }
            #pragma unroll
            for (int j = 0; j < 12; ++j) {
                uint32_t boff = SWZ((uint32_t)((wn*96 + j*8 + b_r) * 128 + (kb + b_k) * 2));
                uint32_t bh[2], bl[2];
                LDSM_X2(bh, sb + QKV_B_HI + boff);
                LDSM_X2(bl, sb + QKV_B_LO + boff);
                #pragma unroll
                for (int mi = 0; mi < 2; ++mi) {
                    MMA16816(acc[mi][j], ah[mi], bh);
                    MMA16816(acc[mi][j], ah[mi], bl);
                    MMA16816(acc[mi][j], al[mi], bh);
                }
            }
        }
    }

    // ---- epilogue: scatter f32 to g_q/g_k/g_v
    const int qr = L >> 2, qc = (L & 3) * 2;
    #pragma unroll
    for (int mi = 0; mi < 2; ++mi) {
        #pragma unroll
        for (int j = 0; j < 12; ++j) {
            int n = wn * 96 + j * 8 + qc;
            int mat = n >> 6, d = n & 63;
            float* og = (mat == 0 ? g_q : mat == 1 ? g_k : g_v);
            #pragma unroll
            for (int half = 0; half < 2; ++half) {
                int m = m0 + wm * 32 + mi * 16 + qr + half * 8;
                int b = m >> 11, t = m & 2047;
                float2 r = make_float2(acc[mi][j][half*2], acc[mi][j][half*2+1]);
                *(float2*)&og[((size_t)(b * Hn + h) * Tn + t) * Dn + d] = r;
            }
        }
    }
}

// ---------------------------------------------------------------------------
// Kernel 2: causal flash attention (SIMT fp32 mainloop — validated);
// epilogue emits split-bf16 into g_attn_hi/lo.  grid (32 q-tiles, 64 bh).
// ---------------------------------------------------------------------------
__global__ __launch_bounds__(256, 2) void attn_kernel()
{
    __shared__ float Qt[64][64];
    __shared__ float KP[64][64];
    __shared__ float Vs[64][64];

    const int qt = gridDim.x - 1 - blockIdx.x;
    const int bh = blockIdx.y;
    const int q0 = qt * 64;
    const int tid = threadIdx.x;
    const int tx = tid & 15, ty = tid >> 4;
    const int lr = tid >> 2, lc = (tid & 3) * 4;

    const float* qg = g_q + (size_t)bh * Tn * Dn;
    const float* kg = g_k + (size_t)bh * Tn * Dn;
    const float* vg = g_v + (size_t)bh * Tn * Dn;
    const float scale = 0.03125f;

    #pragma unroll
    for (int c0 = 0; c0 < 64; c0 += 16) {
        float4 a = *(const float4*)&qg[(size_t)(q0 + lr) * Dn + c0 + lc];
        Qt[c0+lc+0][lr] = a.x * scale; Qt[c0+lc+1][lr] = a.y * scale;
        Qt[c0+lc+2][lr] = a.z * scale; Qt[c0+lc+3][lr] = a.w * scale;
    }

    float o[4][4] = {};
    float m_run[4], l_run[4];
    #pragma unroll
    for (int i = 0; i < 4; ++i) { m_run[i] = -1e30f; l_run[i] = 0.f; }

    for (int kt = 0; kt <= qt; ++kt) {
        const int k0 = kt * 64;
        __syncthreads();
        #pragma unroll
        for (int c0 = 0; c0 < 64; c0 += 16) {
            float4 a = *(const float4*)&kg[(size_t)(k0 + lr) * Dn + c0 + lc];
            KP[c0+lc+0][lr] = a.x; KP[c0+lc+1][lr] = a.y;
            KP[c0+lc+2][lr] = a.z; KP[c0+lc+3][lr] = a.w;
            float4 v = *(const float4*)&vg[(size_t)(k0 + lr) * Dn + c0 + lc];
            *(float4*)&Vs[lr][c0+lc] = v;
        }
        __syncthreads();

        float s[4][4] = {};
        #pragma unroll 16
        for (int d = 0; d < 64; ++d) {
            float4 av = *(const float4*)&Qt[d][ty*4];
            float4 bv = *(const float4*)&KP[d][tx*4];
            float aa[4] = {av.x, av.y, av.z, av.w};
            float bb[4] = {bv.x, bv.y, bv.z, bv.w};
            #pragma unroll
            for (int i = 0; i < 4; ++i)
                #pragma unroll
                for (int j = 0; j < 4; ++j)
                    s[i][j] += aa[i] * bb[j];
        }

        if (kt == qt) {
            #pragma unroll
            for (int i = 0; i < 4; ++i)
                #pragma unroll
                for (int j = 0; j < 4; ++j)
                    if (tx*4 + j > ty*4 + i) s[i][j] = -1e30f;
        }

        float mt[4];
        #pragma unroll
        for (int i = 0; i < 4; ++i)
            mt[i] = fmaxf(fmaxf(s[i][0], s[i][1]), fmaxf(s[i][2], s[i][3]));
        #pragma unroll
        for (int off = 8; off; off >>= 1)
            #pragma unroll
            for (int i = 0; i < 4; ++i)
                mt[i] = fmaxf(mt[i], __shfl_xor_sync(0xffffffffu, mt[i], off));

        float lsum[4];
        #pragma unroll
        for (int i = 0; i < 4; ++i) {
            float mn = fmaxf(m_run[i], mt[i]);
            float f  = __expf(m_run[i] - mn);
            m_run[i] = mn;
            lsum[i] = 0.f;
            #pragma unroll
            for (int j = 0; j < 4; ++j) {
                s[i][j] = __expf(s[i][j] - mn);
                lsum[i] += s[i][j];
            }
            #pragma unroll
            for (int j = 0; j < 4; ++j) o[i][j] *= f;
            l_run[i] *= f;
        }
        #pragma unroll
        for (int off = 8; off; off >>= 1)
            #pragma unroll
            for (int i = 0; i < 4; ++i)
                lsum[i] += __shfl_xor_sync(0xffffffffu, lsum[i], off);
        #pragma unroll
        for (int i = 0; i < 4; ++i) l_run[i] += lsum[i];

        __syncthreads();
        #pragma unroll
        for (int i = 0; i < 4; ++i)
            *(float4*)&KP[ty*4+i][tx*4] = make_float4(s[i][0], s[i][1], s[i][2], s[i][3]);
        __syncthreads();

        #pragma unroll 4
        for (int s4 = 0; s4 < 16; ++s4) {
            float4 p[4], v[4];
            #pragma unroll
            for (int i = 0; i < 4; ++i) p[i] = *(const float4*)&KP[ty*4+i][s4*4];
            #pragma unroll
            for (int t = 0; t < 4; ++t) v[t] = *(const float4*)&Vs[s4*4+t][tx*4];
            #pragma unroll
            for (int i = 0; i < 4; ++i) {
                o[i][0] += p[i].x*v[0].x + p[i].y*v[1].x + p[i].z*v[2].x + p[i].w*v[3].x;
                o[i][1] += p[i].x*v[0].y + p[i].y*v[1].y + p[i].z*v[2].y + p[i].w*v[3].y;
                o[i][2] += p[i].x*v[0].z + p[i].y*v[1].z + p[i].z*v[2].z + p[i].w*v[3].z;
                o[i][3] += p[i].x*v[0].w + p[i].y*v[1].w + p[i].z*v[2].w + p[i].w*v[3].w;
            }
        }
    }

    #pragma unroll
    for (int i = 0; i < 4; ++i) {
        float inv = 1.0f / l_run[i];
        unsigned short h0,h1,h2,h3,l0,l1,l2,l3;
        bsplit(o[i][0]*inv, h0, l0); bsplit(o[i][1]*inv, h1, l1);
        bsplit(o[i][2]*inv, h2, l2); bsplit(o[i][3]*inv, h3, l3);
        size_t idx = ((size_t)bh * Tn + q0 + ty*4 + i) * Dn + tx*4;
        *(uint2*)&g_attn_hi[idx] = pack4(h0, h1, h2, h3);
        *(uint2*)&g_attn_lo[idx] = pack4(l0, l1, l2, l3);
    }
}

// ---------------------------------------------------------------------------
// Kernel 3: output projection via mma.sync bf16 (split 3-term).
// Per CTA: M=128, N=128, K=1024.  8 warps: 4m x 2n; warp 32 x 64 (2 x 8 frags).
// grid (8 n-tiles, 64 m-tiles), 256 threads, 64KB dyn smem.
// ---------------------------------------------------------------------------
#define OP_A_HI 0
#define OP_A_LO 16384
#define OP_B_HI 32768
#define OP_B_LO 49152
#define OP_SMEM 65536

__global__ __launch_bounds__(256, 1) void outproj_tc(
    const float* __restrict__ bo, float* __restrict__ out)
{
    extern __shared__ __align__(1024) char smem[];
    const uint32_t sb = smem_u32(smem);
    const int tid = threadIdx.x;
    const int n0 = blockIdx.x * 128;
    const int m0 = blockIdx.y * 128;
    const int wid = tid >> 5, L = tid & 31;
    const int wm = wid & 3, wn = wid >> 2;

    const int a_r = L & 15;
    const int a_k = (L >> 4) * 8;
    const int b_r = L & 7;
    const int b_k = (L & 8);

    float acc[2][8][4] = {};

    for (int chunk = 0; chunk < 16; ++chunk) {
        const int k0 = chunk * 64;
        const int head = chunk;
        if (chunk) __syncthreads();
        // ---- A: attn split-bf16 gather [128 x 64]
        #pragma unroll
        for (int p = 0; p < 8; ++p) {
            int i = p * 256 + tid;             // 2048 uint2 per split
            int row = i >> 4, kk = (i & 15) * 4;
            int m = m0 + row, b = m >> 11, t = m & 2047;
            size_t src = ((size_t)(b * Hn + head) * Tn + t) * Dn + kk;
            uint32_t off = SWZ((uint32_t)(row * 128 + kk * 2));
            *(uint2*)(smem + OP_A_HI + off) = *(const uint2*)&g_attn_hi[src];
            *(uint2*)(smem + OP_A_LO + off) = *(const uint2*)&g_attn_lo[src];
        }
        // ---- B: Wo split [128 x 64]
        #pragma unroll
        for (int p = 0; p < 8; ++p) {
            int i = p * 256 + tid;
            int row = i >> 4, kk = (i & 15) * 4;
            size_t src = (size_t)(n0 + row) * Cn + k0 + kk;
            uint32_t off = SWZ((uint32_t)(row * 128 + kk * 2));
            *(uint2*)(smem + OP_B_HI + off) = *(const uint2*)&g_wo_hi[src];
            *(uint2*)(smem + OP_B_LO + off) = *(const uint2*)&g_wo_lo[src];
        }
        __syncthreads();

        #pragma unroll
        for (int ks = 0; ks < 4; ++ks) {
            const int kb = ks * 16;
            uint32_t ah[2][4], al[2][4];
            #pragma unroll
            for (int mi = 0; mi < 2; ++mi) {
                uint32_t aoff = SWZ((uint32_t)((wm*32 + mi*16 + a_r) * 128 + (kb + a_k) * 2));
                LDSM_X4(ah[mi], sb + OP_A_HI + aoff);
                LDSM_X4(al[mi], sb + OP_A_LO + aoff);
            }
            #pragma unroll
            for (int j = 0; j < 8; ++j) {
                uint32_t boff = SWZ((uint32_t)((wn*64 + j*8 + b_r) * 128 + (kb + b_k) * 2));
                uint32_t bh[2], bl[2];
                LDSM_X2(bh, sb + OP_B_HI + boff);
                LDSM_X2(bl, sb + OP_B_LO + boff);
                #pragma unroll
                for (int mi = 0; mi < 2; ++mi) {
                    MMA16816(acc[mi][j], ah[mi], bh);
                    MMA16816(acc[mi][j], ah[mi], bl);
                    MMA16816(acc[mi][j], al[mi], bh);
                }
            }
        }
    }

    // ---- epilogue: out = acc + bias
    const int qr = L >> 2, qc = (L & 3) * 2;
    #pragma unroll
    for (int mi = 0; mi < 2; ++mi) {
        #pragma unroll
        for (int j = 0; j < 8; ++j) {
            int n = n0 + wn * 64 + j * 8 + qc;
            float2 bias = *(const float2*)&bo[n];
            #pragma unroll
            for (int half = 0; half < 2; ++half) {
                int m = m0 + wm * 32 + mi * 16 + qr + half * 8;
                float2 r = make_float2(acc[mi][j][half*2]   + bias.x,
                                       acc[mi][j][half*2+1] + bias.y);
                *(float2*)&out[(size_t)m * Cn + n] = r;
            }
        }
    }
}

// ---------------------------------------------------------------------------
extern "C" void kernel_launch(void* const* d_in, const int* in_sizes, int n_in,
                              void* d_out, int out_size)
{
    const float* x  = (const float*)d_in[0];
    const float* Wq = (const float*)d_in[1];
    const float* Wk = (const float*)d_in[2];
    const float* Wv = (const float*)d_in[3];
    const float* Wo = (const float*)d_in[4];
    const float* bo = (const float*)d_in[5];
    float* out = (float*)d_out;

    cudaFuncSetAttribute(qkv_tc, cudaFuncAttributeMaxDynamicSharedMemorySize, QKV_SMEM);
    cudaFuncSetAttribute(outproj_tc, cudaFuncAttributeMaxDynamicSharedMemorySize, OP_SMEM);

    dim3 gw(Cn/64, Hn, 3);
    wsplit_t<<<gw, 256>>>(Wq, Wk, Wv);
    wo_split<<<(Cn*Cn)/256, 256>>>(Wo);

    dim3 g1(Hn, (Bn*Tn)/128);               // (16, 64)
    qkv_tc<<<g1, 256, QKV_SMEM>>>(x);

    dim3 g2(Tn/64, Bn*Hn);                  // (32, 64)
    attn_kernel<<<g2, 256>>>();

    dim3 g3(Cn/128, (Bn*Tn)/128);           // (8, 64)
    outproj_tc<<<g3, 256, OP_SMEM>>>(bo, out);
}

// round 14
// speedup vs baseline: 2.4159x; 1.5725x over previous
#include <cuda_runtime.h>
#include <cuda_bf16.h>
#include <cstdint>

#define Bn 4
#define Tn 2048
#define Cn 1024
#define Hn 16
#define Dn 64

// split-bf16 intermediates (Q pre-scaled by C^-0.5 * log2e)
__device__ unsigned short g_q_hi[Bn*Hn*Tn*Dn];
__device__ unsigned short g_q_lo[Bn*Hn*Tn*Dn];
__device__ unsigned short g_k_hi[Bn*Hn*Tn*Dn];
__device__ unsigned short g_k_lo[Bn*Hn*Tn*Dn];
__device__ unsigned short g_vt_hi[Bn*Hn*Dn*Tn];  // [bh][d][t] (transposed)
__device__ unsigned short g_vt_lo[Bn*Hn*Dn*Tn];
// attention output as split-bf16 (consumed by HMMA outproj)
__device__ unsigned short g_attn_hi[Bn*Hn*Tn*Dn];
__device__ unsigned short g_attn_lo[Bn*Hn*Tn*Dn];
// transposed+split weights, K-major for the mma B operand
__device__ unsigned short g_wt_hi[3*Hn*Dn*Cn];   // [mat][h][d][c]
__device__ unsigned short g_wt_lo[3*Hn*Dn*Cn];
__device__ unsigned short g_wo_hi[Cn*Cn];        // [e][c] (already K-major)
__device__ unsigned short g_wo_lo[Cn*Cn];

// ---------------------------------------------------------------------------
// Helpers: baseline-PTX tensor core ops (no 'a'-suffix features!)
// ---------------------------------------------------------------------------
__device__ __forceinline__ uint32_t smem_u32(const void* p) {
    uint32_t a;
    asm("{ .reg .u64 t; cvta.to.shared.u64 t, %1; cvt.u32.u64 %0, t; }"
        : "=r"(a) : "l"(p));
    return a;
}
#define LDSM_X4(r, addr)                                                     \
    asm volatile("ldmatrix.sync.aligned.m8n8.x4.shared.b16 {%0,%1,%2,%3}, [%4];" \
        : "=r"((r)[0]), "=r"((r)[1]), "=r"((r)[2]), "=r"((r)[3]) : "r"(addr))
#define LDSM_X2(r, addr)                                                     \
    asm volatile("ldmatrix.sync.aligned.m8n8.x2.shared.b16 {%0,%1}, [%2];"   \
        : "=r"((r)[0]), "=r"((r)[1]) : "r"(addr))
#define MMA16816(d, a, b)                                                    \
    asm volatile("mma.sync.aligned.m16n8k16.row.col.f32.bf16.bf16.f32 "      \
        "{%0,%1,%2,%3}, {%4,%5,%6,%7}, {%8,%9}, {%0,%1,%2,%3};"              \
        : "+f"((d)[0]), "+f"((d)[1]), "+f"((d)[2]), "+f"((d)[3])             \
        : "r"((a)[0]), "r"((a)[1]), "r"((a)[2]), "r"((a)[3]),                \
          "r"((b)[0]), "r"((b)[1]))

#define SWZ(x) ((x) ^ (((x) >> 3) & 0x70))

__device__ __forceinline__ void bsplit(float v, unsigned short& hi, unsigned short& lo) {
    __nv_bfloat16 h = __float2bfloat16(v);
    hi = __bfloat16_as_ushort(h);
    lo = __bfloat16_as_ushort(__float2bfloat16(v - __bfloat162float(h)));
}
__device__ __forceinline__ void split2(float v0, float v1, uint32_t& hi, uint32_t& lo) {
    unsigned short h0, h1, l0, l1;
    bsplit(v0, h0, l0); bsplit(v1, h1, l1);
    hi = (uint32_t)h0 | ((uint32_t)h1 << 16);
    lo = (uint32_t)l0 | ((uint32_t)l1 << 16);
}
__device__ __forceinline__ uint2 pack4(unsigned short a, unsigned short b,
                                       unsigned short c, unsigned short d) {
    uint2 u;
    u.x = (uint32_t)a | ((uint32_t)b << 16);
    u.y = (uint32_t)c | ((uint32_t)d << 16);
    return u;
}

// ---------------------------------------------------------------------------
// Prep 1: transpose + split Wq/Wk/Wv:  g_wt[mat][h][d][c] = split(W[mat][h][c][d])
// ---------------------------------------------------------------------------
__global__ __launch_bounds__(256) void wsplit_t(
    const float* __restrict__ Wq, const float* __restrict__ Wk,
    const float* __restrict__ Wv)
{
    __shared__ float tile[64][65];
    const int mat = blockIdx.z, h = blockIdx.y, c0 = blockIdx.x * 64;
    const float* Wh = (mat == 0 ? Wq : mat == 1 ? Wk : Wv) + (size_t)h * Cn * Dn;
    const int tid = threadIdx.x;
    for (int i = tid; i < 4096; i += 256) {
        int r = i >> 6, d = i & 63;
        tile[r][d] = Wh[(size_t)(c0 + r) * Dn + d];
    }
    __syncthreads();
    for (int i = tid; i < 4096; i += 256) {
        int d = i >> 6, c = i & 63;
        unsigned short hi, lo; bsplit(tile[c][d], hi, lo);
        size_t o = ((size_t)(mat * Hn + h) * Dn + d) * Cn + c0 + c;
        g_wt_hi[o] = hi; g_wt_lo[o] = lo;
    }
}

// Prep 2: split Wo (already K-major: Wo[e][c])
__global__ __launch_bounds__(256) void wo_split(const float* __restrict__ Wo)
{
    int i = blockIdx.x * 256 + threadIdx.x;
    unsigned short hi, lo; bsplit(Wo[i], hi, lo);
    g_wo_hi[i] = hi; g_wo_lo[i] = lo;
}

// ---------------------------------------------------------------------------
// Kernel 1: QKV projection via mma.sync bf16 (split 3-term).
// Epilogue emits split-bf16: Q (scaled by C^-0.5*log2e), K, and V transposed.
// grid (16 heads, 64 m-tiles), 256 threads, 80KB dyn smem.
// ---------------------------------------------------------------------------
#define QKV_A_HI 0
#define QKV_A_LO 16384
#define QKV_B_HI 32768
#define QKV_B_LO 57344
#define QKV_SMEM 81920

__global__ __launch_bounds__(256, 1) void qkv_tc(const float* __restrict__ x)
{
    extern __shared__ __align__(1024) char smem[];
    const uint32_t sb = smem_u32(smem);
    const int tid = threadIdx.x;
    const int h  = blockIdx.x;
    const int m0 = blockIdx.y * 128;
    const int wid = tid >> 5, L = tid & 31;
    const int wm = wid & 3, wn = wid >> 2;

    const int a_r = L & 15;
    const int a_k = (L >> 4) * 8;
    const int b_r = L & 7;
    const int b_k = (L & 8);

    float acc[2][12][4] = {};

    const int lrow = tid >> 1;
    const int lpart = (tid & 1) * 32;

    for (int chunk = 0; chunk < 16; ++chunk) {
        const int k0 = chunk * 64;
        if (chunk) __syncthreads();
        #pragma unroll
        for (int i = 0; i < 8; ++i) {
            int col = lpart + i * 4;
            float4 a = *(const float4*)&x[(size_t)(m0 + lrow) * Cn + k0 + col];
            unsigned short h0,h1,h2,h3,l0,l1,l2,l3;
            bsplit(a.x, h0, l0); bsplit(a.y, h1, l1);
            bsplit(a.z, h2, l2); bsplit(a.w, h3, l3);
            uint32_t off = SWZ((uint32_t)(lrow * 128 + col * 2));
            *(uint2*)(smem + QKV_A_HI + off) = pack4(h0, h1, h2, h3);
            *(uint2*)(smem + QKV_A_LO + off) = pack4(l0, l1, l2, l3);
        }
        #pragma unroll
        for (int p = 0; p < 12; ++p) {
            int i = p * 256 + tid;
            int row = i >> 4, kk = (i & 15) * 4;
            int mat = row >> 6, d = row & 63;
            size_t src = ((size_t)(mat * Hn + h) * Dn + d) * Cn + k0 + kk;
            uint32_t off = SWZ((uint32_t)(row * 128 + kk * 2));
            *(uint2*)(smem + QKV_B_HI + off) = *(const uint2*)&g_wt_hi[src];
            *(uint2*)(smem + QKV_B_LO + off) = *(const uint2*)&g_wt_lo[src];
        }
        __syncthreads();

        #pragma unroll
        for (int ks = 0; ks < 4; ++ks) {
            const int kb = ks * 16;
            uint32_t ah[2][4], al[2][4];
            #pragma unroll
            for (int mi = 0; mi < 2; ++mi) {
                uint32_t aoff = SWZ((uint32_t)((wm*32 + mi*16 + a_r) * 128 + (kb + a_k) * 2));
                LDSM_X4(ah[mi], sb + QKV_A_HI + aoff);
                LDSM_X4(al[mi], sb + QKV_A_LO + aoff);
            }
            #pragma unroll
            for (int j = 0; j < 12; ++j) {
                uint32_t boff = SWZ((uint32_t)((wn*96 + j*8 + b_r) * 128 + (kb + b_k) * 2));
                uint32_t bh[2], bl[2];
                LDSM_X2(bh, sb + QKV_B_HI + boff);
                LDSM_X2(bl, sb + QKV_B_LO + boff);
                #pragma unroll
                for (int mi = 0; mi < 2; ++mi) {
                    MMA16816(acc[mi][j], ah[mi], bh);
                    MMA16816(acc[mi][j], ah[mi], bl);
                    MMA16816(acc[mi][j], al[mi], bh);
                }
            }
        }
    }

    // ---- epilogue: split-bf16 scatter. Q scaled by C^-0.5 * log2(e).
    const float qscale = 0.03125f * 1.44269504089f;
    const int qr = L >> 2, qc = (L & 3) * 2;
    #pragma unroll
    for (int mi = 0; mi < 2; ++mi) {
        #pragma unroll
        for (int j = 0; j < 12; ++j) {
            int n = wn * 96 + j * 8 + qc;
            int mat = n >> 6, d = n & 63;
            #pragma unroll
            for (int half = 0; half < 2; ++half) {
                int m = m0 + wm * 32 + mi * 16 + qr + half * 8;
                int b = m >> 11, t = m & 2047;
                int bh = b * Hn + h;
                float v0 = acc[mi][j][half*2], v1 = acc[mi][j][half*2+1];
                if (mat == 0) {
                    uint32_t hi, lo; split2(v0 * qscale, v1 * qscale, hi, lo);
                    size_t idx = ((size_t)bh * Tn + t) * Dn + d;
                    *(uint32_t*)&g_q_hi[idx] = hi;
                    *(uint32_t*)&g_q_lo[idx] = lo;
                } else if (mat == 1) {
                    uint32_t hi, lo; split2(v0, v1, hi, lo);
                    size_t idx = ((size_t)bh * Tn + t) * Dn + d;
                    *(uint32_t*)&g_k_hi[idx] = hi;
                    *(uint32_t*)&g_k_lo[idx] = lo;
                } else {
                    unsigned short h0,l0,h1,l1;
                    bsplit(v0, h0, l0); bsplit(v1, h1, l1);
                    size_t vb = (size_t)bh * Dn * Tn;
                    g_vt_hi[vb + (size_t)d * Tn + t]       = h0;
                    g_vt_hi[vb + (size_t)(d + 1) * Tn + t] = h1;
                    g_vt_lo[vb + (size_t)d * Tn + t]       = l0;
                    g_vt_lo[vb + (size_t)(d + 1) * Tn + t] = l1;
                }
            }
        }
    }
}

// ---------------------------------------------------------------------------
// Kernel 2: causal flash attention on mma.sync bf16 (split 3-term, FA2 style).
// CTA: 128 q-rows, 8 warps (m16 each), k-tile = 64 keys.  Q frags in regs;
// K/V^T tiles staged in 32KB static SMEM.  P fed to P@V from registers.
// grid (16 q-tiles desc, 64 bh), 256 threads.
// SMEM: phase Q: hi@0, lo@16384; loop: KH@0 KL@8192 VH@16384 VL@24576.
// ---------------------------------------------------------------------------
__global__ __launch_bounds__(256, 1) void attn_tc()
{
    __shared__ __align__(1024) char sm[32768];
    const uint32_t sb = smem_u32(sm);
    const int tid = threadIdx.x;
    const int wid = tid >> 5, L = tid & 31;
    const int qt = (int)gridDim.x - 1 - blockIdx.x;   // heavy tiles first
    const int bh = blockIdx.y;
    const int q0 = qt * 128;
    const int qr0 = q0 + wid * 16;

    const size_t bo = (size_t)bh * Tn * Dn;
    const unsigned short* qhp = g_q_hi + bo;
    const unsigned short* qlp = g_q_lo + bo;
    const unsigned short* khp = g_k_hi + bo;
    const unsigned short* klp = g_k_lo + bo;
    const unsigned short* vhp = g_vt_hi + bo;   // [d][t]
    const unsigned short* vlp = g_vt_lo + bo;

    // ---- load Q tile [128][64] hi/lo into SMEM (swizzled), pull frags to regs
    #pragma unroll
    for (int p = 0; p < 8; ++p) {
        int i = p * 256 + tid;
        int row = i >> 4, kk = (i & 15) * 4;
        uint32_t off = SWZ((uint32_t)(row * 128 + kk * 2));
        *(uint2*)(sm + 0     + off) = *(const uint2*)&qhp[(size_t)(q0 + row) * Dn + kk];
        *(uint2*)(sm + 16384 + off) = *(const uint2*)&qlp[(size_t)(q0 + row) * Dn + kk];
    }
    __syncthreads();
    uint32_t qfh[4][4], qfl[4][4];
    const int a_r = L & 15, a_k = (L >> 4) * 8;
    #pragma unroll
    for (int kb = 0; kb < 4; ++kb) {
        uint32_t aoff = SWZ((uint32_t)((wid * 16 + a_r) * 128 + (kb * 16 + a_k) * 2));
        LDSM_X4(qfh[kb], sb + 0 + aoff);
        LDSM_X4(qfl[kb], sb + 16384 + aoff);
    }

    float o[8][4] = {};
    float mrun[2] = {-1e30f, -1e30f};
    float lrun[2] = {0.f, 0.f};

    const int r0l = L >> 2;             // row-in-16 (and +8)
    const int qc = (L & 3) * 2;
    const int b_row = L & 7;
    const int b_koff = (L >> 3) * 8;    // 0,8,16,24 for x4

    const int ktmax = 2 * qt + 1;
    for (int kt = 0; kt <= ktmax; ++kt) {
        const int k0 = kt * 64;
        __syncthreads();                // SMEM free (prev readers done / Q extracted)
        #pragma unroll
        for (int p = 0; p < 4; ++p) {
            int i = p * 256 + tid;
            int row = i >> 4, kk = (i & 15) * 4;
            uint32_t off = SWZ((uint32_t)(row * 128 + kk * 2));
            *(uint2*)(sm + 0     + off) = *(const uint2*)&khp[(size_t)(k0 + row) * Dn + kk];
            *(uint2*)(sm + 8192  + off) = *(const uint2*)&klp[(size_t)(k0 + row) * Dn + kk];
            *(uint2*)(sm + 16384 + off) = *(const uint2*)&vhp[(size_t)row * Tn + k0 + kk];
            *(uint2*)(sm + 24576 + off) = *(const uint2*)&vlp[(size_t)row * Tn + k0 + kk];
        }
        __syncthreads();
        if (k0 > qr0 + 15) continue;    // warp-uniform full-mask skip

        // ---- S = Q K^T (3-term split), n-frags j = key groups of 8
        float s[8][4] = {};
        #pragma unroll
        for (int j = 0; j < 8; ++j) {
            #pragma unroll
            for (int kbp = 0; kbp < 2; ++kbp) {
                uint32_t kh4[4], kl4[4];
                uint32_t boff = SWZ((uint32_t)((j * 8 + b_row) * 128 + (kbp * 32 + b_koff) * 2));
                LDSM_X4(kh4, sb + 0 + boff);
                LDSM_X4(kl4, sb + 8192 + boff);
                MMA16816(s[j], qfh[2*kbp],   &kh4[0]);
                MMA16816(s[j], qfh[2*kbp],   &kl4[0]);
                MMA16816(s[j], qfl[2*kbp],   &kh4[0]);
                MMA16816(s[j], qfh[2*kbp+1], &kh4[2]);
                MMA16816(s[j], qfh[2*kbp+1], &kl4[2]);
                MMA16816(s[j], qfl[2*kbp+1], &kh4[2]);
            }
        }

        // ---- causal mask (boundary tiles only)
        if (k0 + 63 > qr0) {
            int row0 = qr0 + r0l, row1 = row0 + 8;
            #pragma unroll
            for (int j = 0; j < 8; ++j) {
                int c0 = k0 + j * 8 + qc, c1 = c0 + 1;
                if (c0 > row0) s[j][0] = -1e30f;
                if (c1 > row0) s[j][1] = -1e30f;
                if (c0 > row1) s[j][2] = -1e30f;
                if (c1 > row1) s[j][3] = -1e30f;
            }
        }

        // ---- online softmax (base-2; scale folded into Q)
        float mt0 = -1e30f, mt1 = -1e30f;
        #pragma unroll
        for (int j = 0; j < 8; ++j) {
            mt0 = fmaxf(mt0, fmaxf(s[j][0], s[j][1]));
            mt1 = fmaxf(mt1, fmaxf(s[j][2], s[j][3]));
        }
        mt0 = fmaxf(mt0, __shfl_xor_sync(0xffffffffu, mt0, 1));
        mt0 = fmaxf(mt0, __shfl_xor_sync(0xffffffffu, mt0, 2));
        mt1 = fmaxf(mt1, __shfl_xor_sync(0xffffffffu, mt1, 1));
        mt1 = fmaxf(mt1, __shfl_xor_sync(0xffffffffu, mt1, 2));
        float mn0 = fmaxf(mrun[0], mt0), mn1 = fmaxf(mrun[1], mt1);
        float f0 = exp2f(mrun[0] - mn0), f1 = exp2f(mrun[1] - mn1);
        mrun[0] = mn0; mrun[1] = mn1;
        float ls0 = 0.f, ls1 = 0.f;
        #pragma unroll
        for (int j = 0; j < 8; ++j) {
            s[j][0] = exp2f(s[j][0] - mn0); s[j][1] = exp2f(s[j][1] - mn0);
            s[j][2] = exp2f(s[j][2] - mn1); s[j][3] = exp2f(s[j][3] - mn1);
            ls0 += s[j][0] + s[j][1];
            ls1 += s[j][2] + s[j][3];
        }
        ls0 += __shfl_xor_sync(0xffffffffu, ls0, 1);
        ls0 += __shfl_xor_sync(0xffffffffu, ls0, 2);
        ls1 += __shfl_xor_sync(0xffffffffu, ls1, 1);
        ls1 += __shfl_xor_sync(0xffffffffu, ls1, 2);
        lrun[0] = lrun[0] * f0 + ls0;
        lrun[1] = lrun[1] * f1 + ls1;
        #pragma unroll
        for (int j = 0; j < 8; ++j) {
            o[j][0] *= f0; o[j][1] *= f0;
            o[j][2] *= f1; o[j][3] *= f1;
        }

        // ---- P -> split bf16 A-frag components (in registers)
        uint32_t ph01[8], ph23[8], pl01[8], pl23[8];
        #pragma unroll
        for (int j = 0; j < 8; ++j) {
            split2(s[j][0], s[j][1], ph01[j], pl01[j]);
            split2(s[j][2], s[j][3], ph23[j], pl23[j]);
        }

        // ---- O += P V (3-term split), n-frags j = d groups of 8
        #pragma unroll
        for (int j = 0; j < 8; ++j) {
            #pragma unroll
            for (int kbp = 0; kbp < 2; ++kbp) {
                uint32_t vh4[4], vl4[4];
                uint32_t boff = SWZ((uint32_t)((j * 8 + b_row) * 128 + (kbp * 32 + b_koff) * 2));
                LDSM_X4(vh4, sb + 16384 + boff);
                LDSM_X4(vl4, sb + 24576 + boff);
                #pragma unroll
                for (int t = 0; t < 2; ++t) {
                    int kb = 2 * kbp + t;
                    uint32_t ah[4] = {ph01[2*kb], ph23[2*kb], ph01[2*kb+1], ph23[2*kb+1]};
                    uint32_t al[4] = {pl01[2*kb], pl23[2*kb], pl01[2*kb+1], pl23[2*kb+1]};
                    MMA16816(o[j], ah, &vh4[2*t]);
                    MMA16816(o[j], ah, &vl4[2*t]);
                    MMA16816(o[j], al, &vh4[2*t]);
                }
            }
        }
    }

    // ---- epilogue: O /= l, emit split-bf16 for outproj
    float inv0 = 1.0f / lrun[0], inv1 = 1.0f / lrun[1];
    int t0 = qr0 + r0l, t1 = t0 + 8;
    #pragma unroll
    for (int j = 0; j < 8; ++j) {
        int d = j * 8 + qc;
        uint32_t hi, lo;
        split2(o[j][0] * inv0, o[j][1] * inv0, hi, lo);
        size_t i0 = ((size_t)bh * Tn + t0) * Dn + d;
        *(uint32_t*)&g_attn_hi[i0] = hi;
        *(uint32_t*)&g_attn_lo[i0] = lo;
        split2(o[j][2] * inv1, o[j][3] * inv1, hi, lo);
        size_t i1 = ((size_t)bh * Tn + t1) * Dn + d;
        *(uint32_t*)&g_attn_hi[i1] = hi;
        *(uint32_t*)&g_attn_lo[i1] = lo;
    }
}

// ---------------------------------------------------------------------------
// Kernel 3: output projection via mma.sync bf16 (split 3-term).  Unchanged.
// grid (8 n-tiles, 64 m-tiles), 256 threads, 64KB dyn smem.
// ---------------------------------------------------------------------------
#define OP_A_HI 0
#define OP_A_LO 16384
#define OP_B_HI 32768
#define OP_B_LO 49152
#define OP_SMEM 65536

__global__ __launch_bounds__(256, 1) void outproj_tc(
    const float* __restrict__ bo, float* __restrict__ out)
{
    extern __shared__ __align__(1024) char smem[];
    const uint32_t sb = smem_u32(smem);
    const int tid = threadIdx.x;
    const int n0 = blockIdx.x * 128;
    const int m0 = blockIdx.y * 128;
    const int wid = tid >> 5, L = tid & 31;
    const int wm = wid & 3, wn = wid >> 2;

    const int a_r = L & 15;
    const int a_k = (L >> 4) * 8;
    const int b_r = L & 7;
    const int b_k = (L & 8);

    float acc[2][8][4] = {};

    for (int chunk = 0; chunk < 16; ++chunk) {
        const int k0 = chunk * 64;
        const int head = chunk;
        if (chunk) __syncthreads();
        #pragma unroll
        for (int p = 0; p < 8; ++p) {
            int i = p * 256 + tid;
            int row = i >> 4, kk = (i & 15) * 4;
            int m = m0 + row, b = m >> 11, t = m & 2047;
            size_t src = ((size_t)(b * Hn + head) * Tn + t) * Dn + kk;
            uint32_t off = SWZ((uint32_t)(row * 128 + kk * 2));
            *(uint2*)(smem + OP_A_HI + off) = *(const uint2*)&g_attn_hi[src];
            *(uint2*)(smem + OP_A_LO + off) = *(const uint2*)&g_attn_lo[src];
        }
        #pragma unroll
        for (int p = 0; p < 8; ++p) {
            int i = p * 256 + tid;
            int row = i >> 4, kk = (i & 15) * 4;
            size_t src = (size_t)(n0 + row) * Cn + k0 + kk;
            uint32_t off = SWZ((uint32_t)(row * 128 + kk * 2));
            *(uint2*)(smem + OP_B_HI + off) = *(const uint2*)&g_wo_hi[src];
            *(uint2*)(smem + OP_B_LO + off) = *(const uint2*)&g_wo_lo[src];
        }
        __syncthreads();

        #pragma unroll
        for (int ks = 0; ks < 4; ++ks) {
            const int kb = ks * 16;
            uint32_t ah[2][4], al[2][4];
            #pragma unroll
            for (int mi = 0; mi < 2; ++mi) {
                uint32_t aoff = SWZ((uint32_t)((wm*32 + mi*16 + a_r) * 128 + (kb + a_k) * 2));
                LDSM_X4(ah[mi], sb + OP_A_HI + aoff);
                LDSM_X4(al[mi], sb + OP_A_LO + aoff);
            }
            #pragma unroll
            for (int j = 0; j < 8; ++j) {
                uint32_t boff = SWZ((uint32_t)((wn*64 + j*8 + b_r) * 128 + (kb + b_k) * 2));
                uint32_t bh[2], bl[2];
                LDSM_X2(bh, sb + OP_B_HI + boff);
                LDSM_X2(bl, sb + OP_B_LO + boff);
                #pragma unroll
                for (int mi = 0; mi < 2; ++mi) {
                    MMA16816(acc[mi][j], ah[mi], bh);
                    MMA16816(acc[mi][j], ah[mi], bl);
                    MMA16816(acc[mi][j], al[mi], bh);
                }
            }
        }
    }

    const int qr = L >> 2, qc = (L & 3) * 2;
    #pragma unroll
    for (int mi = 0; mi < 2; ++mi) {
        #pragma unroll
        for (int j = 0; j < 8; ++j) {
            int n = n0 + wn * 64 + j * 8 + qc;
            float2 bias = *(const float2*)&bo[n];
            #pragma unroll
            for (int half = 0; half < 2; ++half) {
                int m = m0 + wm * 32 + mi * 16 + qr + half * 8;
                float2 r = make_float2(acc[mi][j][half*2]   + bias.x,
                                       acc[mi][j][half*2+1] + bias.y);
                *(float2*)&out[(size_t)m * Cn + n] = r;
            }
        }
    }
}

// ---------------------------------------------------------------------------
extern "C" void kernel_launch(void* const* d_in, const int* in_sizes, int n_in,
                              void* d_out, int out_size)
{
    const float* x  = (const float*)d_in[0];
    const float* Wq = (const float*)d_in[1];
    const float* Wk = (const float*)d_in[2];
    const float* Wv = (const float*)d_in[3];
    const float* Wo = (const float*)d_in[4];
    const float* bo = (const float*)d_in[5];
    float* out = (float*)d_out;

    cudaFuncSetAttribute(qkv_tc, cudaFuncAttributeMaxDynamicSharedMemorySize, QKV_SMEM);
    cudaFuncSetAttribute(outproj_tc, cudaFuncAttributeMaxDynamicSharedMemorySize, OP_SMEM);

    dim3 gw(Cn/64, Hn, 3);
    wsplit_t<<<gw, 256>>>(Wq, Wk, Wv);
    wo_split<<<(Cn*Cn)/256, 256>>>(Wo);

    dim3 g1(Hn, (Bn*Tn)/128);               // (16, 64)
    qkv_tc<<<g1, 256, QKV_SMEM>>>(x);

    dim3 g2(Tn/128, Bn*Hn);                 // (16, 64)
    attn_tc<<<g2, 256>>>();

    dim3 g3(Cn/128, (Bn*Tn)/128);           // (8, 64)
    outproj_tc<<<g3, 256, OP_SMEM>>>(bo, out);
}

// round 16
// speedup vs baseline: 2.5677x; 1.0628x over previous
#include <cuda_runtime.h>
#include <cuda_bf16.h>
#include <cstdint>

#define Bn 4
#define Tn 2048
#define Cn 1024
#define Hn 16
#define Dn 64

// split-bf16 intermediates (Q pre-scaled by C^-0.5 * log2e); all [bh][t][d]
__device__ unsigned short g_q_hi[Bn*Hn*Tn*Dn];
__device__ unsigned short g_q_lo[Bn*Hn*Tn*Dn];
__device__ unsigned short g_k_hi[Bn*Hn*Tn*Dn];
__device__ unsigned short g_k_lo[Bn*Hn*Tn*Dn];
__device__ unsigned short g_v_hi[Bn*Hn*Tn*Dn];
__device__ unsigned short g_v_lo[Bn*Hn*Tn*Dn];
// attention output as split-bf16 (consumed by HMMA outproj)
__device__ unsigned short g_attn_hi[Bn*Hn*Tn*Dn];
__device__ unsigned short g_attn_lo[Bn*Hn*Tn*Dn];
// transposed+split weights, K-major for the mma B operand
__device__ unsigned short g_wt_hi[3*Hn*Dn*Cn];   // [mat][h][d][c]
__device__ unsigned short g_wt_lo[3*Hn*Dn*Cn];
__device__ unsigned short g_wo_hi[Cn*Cn];        // [e][c] (already K-major)
__device__ unsigned short g_wo_lo[Cn*Cn];

// ---------------------------------------------------------------------------
// Helpers: baseline-PTX tensor core ops (no 'a'-suffix features!)
// ---------------------------------------------------------------------------
__device__ __forceinline__ uint32_t smem_u32(const void* p) {
    uint32_t a;
    asm("{ .reg .u64 t; cvta.to.shared.u64 t, %1; cvt.u32.u64 %0, t; }"
        : "=r"(a) : "l"(p));
    return a;
}
#define LDSM_X4(r, addr)                                                     \
    asm volatile("ldmatrix.sync.aligned.m8n8.x4.shared.b16 {%0,%1,%2,%3}, [%4];" \
        : "=r"((r)[0]), "=r"((r)[1]), "=r"((r)[2]), "=r"((r)[3]) : "r"(addr))
#define LDSM_X4T(r, addr)                                                    \
    asm volatile("ldmatrix.sync.aligned.m8n8.x4.trans.shared.b16 {%0,%1,%2,%3}, [%4];" \
        : "=r"((r)[0]), "=r"((r)[1]), "=r"((r)[2]), "=r"((r)[3]) : "r"(addr))
#define LDSM_X2(r, addr)                                                     \
    asm volatile("ldmatrix.sync.aligned.m8n8.x2.shared.b16 {%0,%1}, [%2];"   \
        : "=r"((r)[0]), "=r"((r)[1]) : "r"(addr))
#define MMA16816(d, a, b)                                                    \
    asm volatile("mma.sync.aligned.m16n8k16.row.col.f32.bf16.bf16.f32 "      \
        "{%0,%1,%2,%3}, {%4,%5,%6,%7}, {%8,%9}, {%0,%1,%2,%3};"              \
        : "+f"((d)[0]), "+f"((d)[1]), "+f"((d)[2]), "+f"((d)[3])             \
        : "r"((a)[0]), "r"((a)[1]), "r"((a)[2]), "r"((a)[3]),                \
          "r"((b)[0]), "r"((b)[1]))
#define CP_ASYNC16(dst, src)                                                 \
    asm volatile("cp.async.cg.shared.global [%0], [%1], 16;" :: "r"(dst), "l"(src))
#define CP_COMMIT() asm volatile("cp.async.commit_group;" ::: "memory")
#define CP_WAIT0()  asm volatile("cp.async.wait_group 0;" ::: "memory")
#define CP_WAIT1()  asm volatile("cp.async.wait_group 1;" ::: "memory")

#define SWZ(x) ((x) ^ (((x) >> 3) & 0x70))

__device__ __forceinline__ void bsplit(float v, unsigned short& hi, unsigned short& lo) {
    __nv_bfloat16 h = __float2bfloat16(v);
    hi = __bfloat16_as_ushort(h);
    lo = __bfloat16_as_ushort(__float2bfloat16(v - __bfloat162float(h)));
}
__device__ __forceinline__ void split2(float v0, float v1, uint32_t& hi, uint32_t& lo) {
    unsigned short h0, h1, l0, l1;
    bsplit(v0, h0, l0); bsplit(v1, h1, l1);
    hi = (uint32_t)h0 | ((uint32_t)h1 << 16);
    lo = (uint32_t)l0 | ((uint32_t)l1 << 16);
}
__device__ __forceinline__ uint2 pack4(unsigned short a, unsigned short b,
                                       unsigned short c, unsigned short d) {
    uint2 u;
    u.x = (uint32_t)a | ((uint32_t)b << 16);
    u.y = (uint32_t)c | ((uint32_t)d << 16);
    return u;
}

// ---------------------------------------------------------------------------
// Prep 1: transpose + split Wq/Wk/Wv:  g_wt[mat][h][d][c] = split(W[mat][h][c][d])
// ---------------------------------------------------------------------------
__global__ __launch_bounds__(256) void wsplit_t(
    const float* __restrict__ Wq, const float* __restrict__ Wk,
    const float* __restrict__ Wv)
{
    __shared__ float tile[64][65];
    const int mat = blockIdx.z, h = blockIdx.y, c0 = blockIdx.x * 64;
    const float* Wh = (mat == 0 ? Wq : mat == 1 ? Wk : Wv) + (size_t)h * Cn * Dn;
    const int tid = threadIdx.x;
    for (int i = tid; i < 4096; i += 256) {
        int r = i >> 6, d = i & 63;
        tile[r][d] = Wh[(size_t)(c0 + r) * Dn + d];
    }
    __syncthreads();
    for (int i = tid; i < 4096; i += 256) {
        int d = i >> 6, c = i & 63;
        unsigned short hi, lo; bsplit(tile[c][d], hi, lo);
        size_t o = ((size_t)(mat * Hn + h) * Dn + d) * Cn + c0 + c;
        g_wt_hi[o] = hi; g_wt_lo[o] = lo;
    }
}

// Prep 2: split Wo (already K-major: Wo[e][c])
__global__ __launch_bounds__(256) void wo_split(const float* __restrict__ Wo)
{
    int i = blockIdx.x * 256 + threadIdx.x;
    unsigned short hi, lo; bsplit(Wo[i], hi, lo);
    g_wo_hi[i] = hi; g_wo_lo[i] = lo;
}

// ---------------------------------------------------------------------------
// Kernel 1: QKV projection via mma.sync bf16 (split 3-term).
// Epilogue emits split-bf16 [t][d] for Q (pre-scaled), K, and V (natural —
// the round-14 V^T scatter is gone; attention transposes via ldmatrix.trans).
// grid (16 heads, 64 m-tiles), 256 threads, 80KB dyn smem.
// ---------------------------------------------------------------------------
#define QKV_A_HI 0
#define QKV_A_LO 16384
#define QKV_B_HI 32768
#define QKV_B_LO 57344
#define QKV_SMEM 81920

__global__ __launch_bounds__(256, 1) void qkv_tc(const float* __restrict__ x)
{
    extern __shared__ __align__(1024) char smem[];
    const uint32_t sb = smem_u32(smem);
    const int tid = threadIdx.x;
    const int h  = blockIdx.x;
    const int m0 = blockIdx.y * 128;
    const int wid = tid >> 5, L = tid & 31;
    const int wm = wid & 3, wn = wid >> 2;

    const int a_r = L & 15;
    const int a_k = (L >> 4) * 8;
    const int b_r = L & 7;
    const int b_k = (L & 8);

    float acc[2][12][4] = {};

    const int lrow = tid >> 1;
    const int lpart = (tid & 1) * 32;

    for (int chunk = 0; chunk < 16; ++chunk) {
        const int k0 = chunk * 64;
        if (chunk) __syncthreads();
        #pragma unroll
        for (int i = 0; i < 8; ++i) {
            int col = lpart + i * 4;
            float4 a = *(const float4*)&x[(size_t)(m0 + lrow) * Cn + k0 + col];
            unsigned short h0,h1,h2,h3,l0,l1,l2,l3;
            bsplit(a.x, h0, l0); bsplit(a.y, h1, l1);
            bsplit(a.z, h2, l2); bsplit(a.w, h3, l3);
            uint32_t off = SWZ((uint32_t)(lrow * 128 + col * 2));
            *(uint2*)(smem + QKV_A_HI + off) = pack4(h0, h1, h2, h3);
            *(uint2*)(smem + QKV_A_LO + off) = pack4(l0, l1, l2, l3);
        }
        #pragma unroll
        for (int p = 0; p < 12; ++p) {
            int i = p * 256 + tid;
            int row = i >> 4, kk = (i & 15) * 4;
            int mat = row >> 6, d = row & 63;
            size_t src = ((size_t)(mat * Hn + h) * Dn + d) * Cn + k0 + kk;
            uint32_t off = SWZ((uint32_t)(row * 128 + kk * 2));
            *(uint2*)(smem + QKV_B_HI + off) = *(const uint2*)&g_wt_hi[src];
            *(uint2*)(smem + QKV_B_LO + off) = *(const uint2*)&g_wt_lo[src];
        }
        __syncthreads();

        #pragma unroll
        for (int ks = 0; ks < 4; ++ks) {
            const int kb = ks * 16;
            uint32_t ah[2][4], al[2][4];
            #pragma unroll
            for (int mi = 0; mi < 2; ++mi) {
                uint32_t aoff = SWZ((uint32_t)((wm*32 + mi*16 + a_r) * 128 + (kb + a_k) * 2));
                LDSM_X4(ah[mi], sb + QKV_A_HI + aoff);
                LDSM_X4(al[mi], sb + QKV_A_LO + aoff);
            }
            #pragma unroll
            for (int j = 0; j < 12; ++j) {
                uint32_t boff = SWZ((uint32_t)((wn*96 + j*8 + b_r) * 128 + (kb + b_k) * 2));
                uint32_t bh[2], bl[2];
                LDSM_X2(bh, sb + QKV_B_HI + boff);
                LDSM_X2(bl, sb + QKV_B_LO + boff);
                #pragma unroll
                for (int mi = 0; mi < 2; ++mi) {
                    MMA16816(acc[mi][j], ah[mi], bh);
                    MMA16816(acc[mi][j], ah[mi], bl);
                    MMA16816(acc[mi][j], al[mi], bh);
                }
            }
        }
    }

    // ---- epilogue: split-bf16 [t][d] scatter for all three mats (coalesced)
    const float qscale = 0.03125f * 1.44269504089f;   // C^-0.5 * log2(e)
    const int qr = L >> 2, qc = (L & 3) * 2;
    #pragma unroll
    for (int mi = 0; mi < 2; ++mi) {
        #pragma unroll
        for (int j = 0; j < 12; ++j) {
            int n = wn * 96 + j * 8 + qc;
            int mat = n >> 6, d = n & 63;
            unsigned short* ghi = (mat == 0) ? g_q_hi : (mat == 1) ? g_k_hi : g_v_hi;
            unsigned short* glo = (mat == 0) ? g_q_lo : (mat == 1) ? g_k_lo : g_v_lo;
            float sc = (mat == 0) ? qscale : 1.0f;
            #pragma unroll
            for (int half = 0; half < 2; ++half) {
                int m = m0 + wm * 32 + mi * 16 + qr + half * 8;
                int b = m >> 11, t = m & 2047;
                uint32_t hi, lo;
                split2(acc[mi][j][half*2] * sc, acc[mi][j][half*2+1] * sc, hi, lo);
                size_t idx = ((size_t)(b * Hn + h) * Tn + t) * Dn + d;
                *(uint32_t*)&ghi[idx] = hi;
                *(uint32_t*)&glo[idx] = lo;
            }
        }
    }
}

// ---------------------------------------------------------------------------
// Kernel 2: causal flash attention on mma.sync bf16 (split 3-term, FA2 style)
// with cp.async double-buffered K/V tiles and ldmatrix.trans V loading.
// CTA: 128 q-rows, 8 warps (m16 each), k-tile = 64 keys.
// SMEM (64KB dyn): two 32KB buffers: {KH@0, KL@8K, VH@16K, VL@24K} each.
// Q staged in buffer 0 before the pipeline starts.
// grid (16 q-tiles desc, 64 bh), 256 threads.
// ---------------------------------------------------------------------------
#define ATT_SMEM 65536

__global__ __launch_bounds__(256, 1) void attn_tc()
{
    extern __shared__ __align__(1024) char sm[];
    const uint32_t sb = smem_u32(sm);
    const int tid = threadIdx.x;
    const int wid = tid >> 5, L = tid & 31;
    const int qt = (int)gridDim.x - 1 - blockIdx.x;   // heavy tiles first
    const int bh = blockIdx.y;
    const int q0 = qt * 128;
    const int qr0 = q0 + wid * 16;

    const size_t bo = (size_t)bh * Tn * Dn;
    const unsigned short* qhp = g_q_hi + bo;
    const unsigned short* qlp = g_q_lo + bo;
    const unsigned short* khp = g_k_hi + bo;
    const unsigned short* klp = g_k_lo + bo;
    const unsigned short* vhp = g_v_hi + bo;   // [t][d] natural
    const unsigned short* vlp = g_v_lo + bo;

    // ---- load Q tile [128][64] hi/lo into SMEM (swizzled), pull frags to regs
    #pragma unroll
    for (int p = 0; p < 8; ++p) {
        int i = p * 256 + tid;
        int row = i >> 4, kk = (i & 15) * 4;
        uint32_t off = SWZ((uint32_t)(row * 128 + kk * 2));
        *(uint2*)(sm + 0     + off) = *(const uint2*)&qhp[(size_t)(q0 + row) * Dn + kk];
        *(uint2*)(sm + 16384 + off) = *(const uint2*)&qlp[(size_t)(q0 + row) * Dn + kk];
    }
    __syncthreads();
    uint32_t qfh[4][4], qfl[4][4];
    const int a_r = L & 15, a_k = (L >> 4) * 8;
    #pragma unroll
    for (int kb = 0; kb < 4; ++kb) {
        uint32_t aoff = SWZ((uint32_t)((wid * 16 + a_r) * 128 + (kb * 16 + a_k) * 2));
        LDSM_X4(qfh[kb], sb + 0 + aoff);
        LDSM_X4(qfl[kb], sb + 16384 + aoff);
    }
    __syncthreads();   // Q fully consumed before cp.async overwrites buffer 0

    // cp.async tile loader: 8 x 16B per thread covers K/V hi/lo (32KB)
    const int ld_row = ((tid & 255) >> 3) & 63;        // idx>>3 over 512 chunks
    auto issue_tile = [&](int kt, int bufb) {
        const int base = bufb * 32768;
        #pragma unroll
        for (int p = 0; p < 8; ++p) {
            int idx = (p & 1) * 256 + tid;             // 0..511 within array
            int row = idx >> 3, c16 = idx & 7;
            size_t src_off = (size_t)(kt * 64 + row) * Dn + c16 * 8;
            const unsigned short* src =
                (p < 2) ? (khp + src_off) : (p < 4) ? (klp + src_off)
              : (p < 6) ? (vhp + src_off) : (vlp + src_off);
            uint32_t dst = sb + base + (p >> 1) * 8192
                         + SWZ((uint32_t)(row * 128 + c16 * 16));
            CP_ASYNC16(dst, src);
        }
    };

    float o[8][4] = {};
    float mrun[2] = {-1e30f, -1e30f};
    float lrun[2] = {0.f, 0.f};

    const int r0l = L >> 2;
    const int qc = (L & 3) * 2;
    const int b_row = L & 7;
    const int b_koff = (L >> 3) * 8;       // S-path K: x4 tiles along k
    const int vt_r = L & 15;               // V trans: t row within 16
    const int vt_c = ((L >> 4) & 1) * 8;   // V trans: d sub-offset

    const int ktmax = 2 * qt + 1;
    issue_tile(0, 0);
    CP_COMMIT();

    for (int kt = 0; kt <= ktmax; ++kt) {
        const int k0 = kt * 64;
        if (kt < ktmax) { issue_tile(kt + 1, (kt + 1) & 1); CP_COMMIT(); CP_WAIT1(); }
        else           { CP_WAIT0(); }
        __syncthreads();                   // tile kt visible to all warps
        const uint32_t bb = sb + (kt & 1) * 32768;

        if (k0 <= qr0 + 15) {
            // ---- S = Q K^T (3-term split), n-frags j = key groups of 8
            float s[8][4] = {};
            #pragma unroll
            for (int j = 0; j < 8; ++j) {
                #pragma unroll
                for (int kbp = 0; kbp < 2; ++kbp) {
                    uint32_t kh4[4], kl4[4];
                    uint32_t boff = SWZ((uint32_t)((j * 8 + b_row) * 128 + (kbp * 32 + b_koff) * 2));
                    LDSM_X4(kh4, bb + 0 + boff);
                    LDSM_X4(kl4, bb + 8192 + boff);
                    MMA16816(s[j], qfh[2*kbp],   &kh4[0]);
                    MMA16816(s[j], qfh[2*kbp],   &kl4[0]);
                    MMA16816(s[j], qfl[2*kbp],   &kh4[0]);
                    MMA16816(s[j], qfh[2*kbp+1], &kh4[2]);
                    MMA16816(s[j], qfh[2*kbp+1], &kl4[2]);
                    MMA16816(s[j], qfl[2*kbp+1], &kh4[2]);
                }
            }

            // ---- causal mask (boundary tiles only)
            if (k0 + 63 > qr0) {
                int row0 = qr0 + r0l, row1 = row0 + 8;
                #pragma unroll
                for (int j = 0; j < 8; ++j) {
                    int c0 = k0 + j * 8 + qc, c1 = c0 + 1;
                    if (c0 > row0) s[j][0] = -1e30f;
                    if (c1 > row0) s[j][1] = -1e30f;
                    if (c0 > row1) s[j][2] = -1e30f;
                    if (c1 > row1) s[j][3] = -1e30f;
                }
            }

            // ---- online softmax (base-2; scale folded into Q)
            float mt0 = -1e30f, mt1 = -1e30f;
            #pragma unroll
            for (int j = 0; j < 8; ++j) {
                mt0 = fmaxf(mt0, fmaxf(s[j][0], s[j][1]));
                mt1 = fmaxf(mt1, fmaxf(s[j][2], s[j][3]));
            }
            mt0 = fmaxf(mt0, __shfl_xor_sync(0xffffffffu, mt0, 1));
            mt0 = fmaxf(mt0, __shfl_xor_sync(0xffffffffu, mt0, 2));
            mt1 = fmaxf(mt1, __shfl_xor_sync(0xffffffffu, mt1, 1));
            mt1 = fmaxf(mt1, __shfl_xor_sync(0xffffffffu, mt1, 2));
            float mn0 = fmaxf(mrun[0], mt0), mn1 = fmaxf(mrun[1], mt1);
            float f0 = exp2f(mrun[0] - mn0), f1 = exp2f(mrun[1] - mn1);
            mrun[0] = mn0; mrun[1] = mn1;
            float ls0 = 0.f, ls1 = 0.f;
            #pragma unroll
            for (int j = 0; j < 8; ++j) {
                s[j][0] = exp2f(s[j][0] - mn0); s[j][1] = exp2f(s[j][1] - mn0);
                s[j][2] = exp2f(s[j][2] - mn1); s[j][3] = exp2f(s[j][3] - mn1);
                ls0 += s[j][0] + s[j][1];
                ls1 += s[j][2] + s[j][3];
            }
            ls0 += __shfl_xor_sync(0xffffffffu, ls0, 1);
            ls0 += __shfl_xor_sync(0xffffffffu, ls0, 2);
            ls1 += __shfl_xor_sync(0xffffffffu, ls1, 1);
            ls1 += __shfl_xor_sync(0xffffffffu, ls1, 2);
            lrun[0] = lrun[0] * f0 + ls0;
            lrun[1] = lrun[1] * f1 + ls1;
            #pragma unroll
            for (int j = 0; j < 8; ++j) {
                o[j][0] *= f0; o[j][1] *= f0;
                o[j][2] *= f1; o[j][3] *= f1;
            }

            // ---- P -> split bf16 A-frag components (in registers)
            uint32_t ph01[8], ph23[8], pl01[8], pl23[8];
            #pragma unroll
            for (int j = 0; j < 8; ++j) {
                split2(s[j][0], s[j][1], ph01[j], pl01[j]);
                split2(s[j][2], s[j][3], ph23[j], pl23[j]);
            }

            // ---- O += P V (3-term split); V B-frags via ldmatrix.trans on [t][d]
            #pragma unroll
            for (int j2 = 0; j2 < 4; ++j2) {
                #pragma unroll
                for (int kb = 0; kb < 4; ++kb) {
                    uint32_t vh4[4], vl4[4];
                    uint32_t boff = SWZ((uint32_t)((kb * 16 + vt_r) * 128 + (j2 * 16 + vt_c) * 2));
                    LDSM_X4T(vh4, bb + 16384 + boff);
                    LDSM_X4T(vl4, bb + 24576 + boff);
                    uint32_t ah[4] = {ph01[2*kb], ph23[2*kb], ph01[2*kb+1], ph23[2*kb+1]};
                    uint32_t al[4] = {pl01[2*kb], pl23[2*kb], pl01[2*kb+1], pl23[2*kb+1]};
                    MMA16816(o[2*j2],   ah, &vh4[0]);
                    MMA16816(o[2*j2],   ah, &vl4[0]);
                    MMA16816(o[2*j2],   al, &vh4[0]);
                    MMA16816(o[2*j2+1], ah, &vh4[2]);
                    MMA16816(o[2*j2+1], ah, &vl4[2]);
                    MMA16816(o[2*j2+1], al, &vh4[2]);
                }
            }
        }
        __syncthreads();                   // all reads of buf[kt&1] done
    }

    // ---- epilogue: O /= l, emit split-bf16 for outproj
    float inv0 = 1.0f / lrun[0], inv1 = 1.0f / lrun[1];
    int t0 = qr0 + r0l, t1 = t0 + 8;
    #pragma unroll
    for (int j = 0; j < 8; ++j) {
        int d = j * 8 + qc;
        uint32_t hi, lo;
        split2(o[j][0] * inv0, o[j][1] * inv0, hi, lo);
        size_t i0 = ((size_t)bh * Tn + t0) * Dn + d;
        *(uint32_t*)&g_attn_hi[i0] = hi;
        *(uint32_t*)&g_attn_lo[i0] = lo;
        split2(o[j][2] * inv1, o[j][3] * inv1, hi, lo);
        size_t i1 = ((size_t)bh * Tn + t1) * Dn + d;
        *(uint32_t*)&g_attn_hi[i1] = hi;
        *(uint32_t*)&g_attn_lo[i1] = lo;
    }
}

// ---------------------------------------------------------------------------
// Kernel 3: output projection via mma.sync bf16 (split 3-term).  Unchanged.
// grid (8 n-tiles, 64 m-tiles), 256 threads, 64KB dyn smem.
// ---------------------------------------------------------------------------
#define OP_A_HI 0
#define OP_A_LO 16384
#define OP_B_HI 32768
#define OP_B_LO 49152
#define OP_SMEM 65536

__global__ __launch_bounds__(256, 1) void outproj_tc(
    const float* __restrict__ bo, float* __restrict__ out)
{
    extern __shared__ __align__(1024) char smem[];
    const uint32_t sb = smem_u32(smem);
    const int tid = threadIdx.x;
    const int n0 = blockIdx.x * 128;
    const int m0 = blockIdx.y * 128;
    const int wid = tid >> 5, L = tid & 31;
    const int wm = wid & 3, wn = wid >> 2;

    const int a_r = L & 15;
    const int a_k = (L >> 4) * 8;
    const int b_r = L & 7;
    const int b_k = (L & 8);

    float acc[2][8][4] = {};

    for (int chunk = 0; chunk < 16; ++chunk) {
        const int k0 = chunk * 64;
        const int head = chunk;
        if (chunk) __syncthreads();
        #pragma unroll
        for (int p = 0; p < 8; ++p) {
            int i = p * 256 + tid;
            int row = i >> 4, kk = (i & 15) * 4;
            int m = m0 + row, b = m >> 11, t = m & 2047;
            size_t src = ((size_t)(b * Hn + head) * Tn + t) * Dn + kk;
            uint32_t off = SWZ((uint32_t)(row * 128 + kk * 2));
            *(uint2*)(smem + OP_A_HI + off) = *(const uint2*)&g_attn_hi[src];
            *(uint2*)(smem + OP_A_LO + off) = *(const uint2*)&g_attn_lo[src];
        }
        #pragma unroll
        for (int p = 0; p < 8; ++p) {
            int i = p * 256 + tid;
            int row = i >> 4, kk = (i & 15) * 4;
            size_t src = (size_t)(n0 + row) * Cn + k0 + kk;
            uint32_t off = SWZ((uint32_t)(row * 128 + kk * 2));
            *(uint2*)(smem + OP_B_HI + off) = *(const uint2*)&g_wo_hi[src];
            *(uint2*)(smem + OP_B_LO + off) = *(const uint2*)&g_wo_lo[src];
        }
        __syncthreads();

        #pragma unroll
        for (int ks = 0; ks < 4; ++ks) {
            const int kb = ks * 16;
            uint32_t ah[2][4], al[2][4];
            #pragma unroll
            for (int mi = 0; mi < 2; ++mi) {
                uint32_t aoff = SWZ((uint32_t)((wm*32 + mi*16 + a_r) * 128 + (kb + a_k) * 2));
                LDSM_X4(ah[mi], sb + OP_A_HI + aoff);
                LDSM_X4(al[mi], sb + OP_A_LO + aoff);
            }
            #pragma unroll
            for (int j = 0; j < 8; ++j) {
                uint32_t boff = SWZ((uint32_t)((wn*64 + j*8 + b_r) * 128 + (kb + b_k) * 2));
                uint32_t bh[2], bl[2];
                LDSM_X2(bh, sb + OP_B_HI + boff);
                LDSM_X2(bl, sb + OP_B_LO + boff);
                #pragma unroll
                for (int mi = 0; mi < 2; ++mi) {
                    MMA16816(acc[mi][j], ah[mi], bh);
                    MMA16816(acc[mi][j], ah[mi], bl);
                    MMA16816(acc[mi][j], al[mi], bh);
                }
            }
        }
    }

    const int qr = L >> 2, qc = (L & 3) * 2;
    #pragma unroll
    for (int mi = 0; mi < 2; ++mi) {
        #pragma unroll
        for (int j = 0; j < 8; ++j) {
            int n = n0 + wn * 64 + j * 8 + qc;
            float2 bias = *(const float2*)&bo[n];
            #pragma unroll
            for (int half = 0; half < 2; ++half) {
                int m = m0 + wm * 32 + mi * 16 + qr + half * 8;
                float2 r = make_float2(acc[mi][j][half*2]   + bias.x,
                                       acc[mi][j][half*2+1] + bias.y);
                *(float2*)&out[(size_t)m * Cn + n] = r;
            }
        }
    }
}

// ---------------------------------------------------------------------------
extern "C" void kernel_launch(void* const* d_in, const int* in_sizes, int n_in,
                              void* d_out, int out_size)
{
    const float* x  = (const float*)d_in[0];
    const float* Wq = (const float*)d_in[1];
    const float* Wk = (const float*)d_in[2];
    const float* Wv = (const float*)d_in[3];
    const float* Wo = (const float*)d_in[4];
    const float* bo = (const float*)d_in[5];
    float* out = (float*)d_out;

    cudaFuncSetAttribute(qkv_tc, cudaFuncAttributeMaxDynamicSharedMemorySize, QKV_SMEM);
    cudaFuncSetAttribute(attn_tc, cudaFuncAttributeMaxDynamicSharedMemorySize, ATT_SMEM);
    cudaFuncSetAttribute(outproj_tc, cudaFuncAttributeMaxDynamicSharedMemorySize, OP_SMEM);

    dim3 gw(Cn/64, Hn, 3);
    wsplit_t<<<gw, 256>>>(Wq, Wk, Wv);
    wo_split<<<(Cn*Cn)/256, 256>>>(Wo);

    dim3 g1(Hn, (Bn*Tn)/128);               // (16, 64)
    qkv_tc<<<g1, 256, QKV_SMEM>>>(x);

    dim3 g2(Tn/128, Bn*Hn);                 // (16, 64)
    attn_tc<<<g2, 256, ATT_SMEM>>>();

    dim3 g3(Cn/128, (Bn*Tn)/128);           // (8, 64)
    outproj_tc<<<g3, 256, OP_SMEM>>>(bo, out);
}